// round 6
// baseline (speedup 1.0000x reference)
#include <cuda_runtime.h>
#include <math.h>
#include <stdint.h>

#define HH 128
#define WW 128
#define NB 4
#define HW (HH * WW)

// ---------------- scratch (static device arrays; no allocation) ------------
__device__ float g_bufA[NB * 64 * HW];      // NHWC64 feature buffer
__device__ float g_bufB[NB * 64 * HW];      // NHWC64 feature buffer
__device__ float g_offb[NB * 144 * HW];     // offsets, NCHW
__device__ float g_nhwc128[NB * 128 * HW];  // concat(neibor,target) NHWC128
__device__ float g_nhwcN[NB * 64 * HW];     // neibor NHWC64
__device__ float g_wt[576 * 64];            // deform weights transposed
__device__ float g_wh[144 * 1152];          // conv weights hi (tf32), reordered
__device__ float g_wl[144 * 1152];          // conv weights lo (tf32), reordered

// ---------------- helpers ---------------------------------------------------
// cvt.rna.tf32.f32 destination is a .b32 register; reinterpret as float.
__device__ __forceinline__ float cvt_tf32(float v) {
    uint32_t r;
    asm("cvt.rna.tf32.f32 %0, %1;" : "=r"(r) : "f"(v));
    return __uint_as_float(r);
}
__device__ __forceinline__ void mma8(float* c, const uint32_t* a,
                                     uint32_t b0, uint32_t b1) {
    asm volatile(
        "mma.sync.aligned.m16n8k8.row.col.f32.tf32.tf32.f32 "
        "{%0,%1,%2,%3}, {%4,%5,%6,%7}, {%8,%9}, {%0,%1,%2,%3};"
        : "+f"(c[0]), "+f"(c[1]), "+f"(c[2]), "+f"(c[3])
        : "r"(a[0]), "r"(a[1]), "r"(a[2]), "r"(a[3]), "r"(b0), "r"(b1));
}

// ---------------------------------------------------------------------------
// Transforms
// ---------------------------------------------------------------------------
__global__ __launch_bounds__(256) void concat_nhwc128_kernel(
    const float* __restrict__ n, const float* __restrict__ t, float* __restrict__ out)
{
    int idx = blockIdx.x * 256 + threadIdx.x;   // NB*HW
    int b  = idx >> 14;
    int yx = idx & (HW - 1);
    const float* s0 = n + (size_t)b * 64 * HW + yx;
    const float* s1 = t + (size_t)b * 64 * HW + yx;
    float* o = out + (size_t)idx * 128;
#pragma unroll 8
    for (int c = 0; c < 64; c++) o[c] = s0[(size_t)c * HW];
#pragma unroll 8
    for (int c = 0; c < 64; c++) o[64 + c] = s1[(size_t)c * HW];
}

__global__ __launch_bounds__(256) void nhwc64_kernel(
    const float* __restrict__ in, float* __restrict__ out)
{
    int idx = blockIdx.x * 256 + threadIdx.x;
    int b  = idx >> 14;
    int yx = idx & (HW - 1);
    const float* s = in + (size_t)b * 64 * HW + yx;
    float* o = out + (size_t)idx * 64;
#pragma unroll 8
    for (int c = 0; c < 64; c++) o[c] = s[(size_t)c * HW];
}

// conv weight prep: w[oc][ic][9] -> wh/wl[oc][k*C_IN+ic] (tf32 hi/lo split)
__global__ void wprep_kernel(const float* __restrict__ w, float* __restrict__ wh,
                             float* __restrict__ wl, int C_IN, int C_OUT)
{
    int i = blockIdx.x * 256 + threadIdx.x;
    int tot = C_OUT * C_IN * 9;
    if (i < tot) {
        int oc = i / (C_IN * 9);
        int rr = i % (C_IN * 9);
        int ic = rr / 9;
        int k  = rr % 9;
        float v = w[i];
        float h = cvt_tf32(v);
        float l = cvt_tf32(v - h);
        int o = oc * C_IN * 9 + k * C_IN + ic;
        wh[o] = h;
        wl[o] = l;
    }
}

// deform weights: w[64][64*9] -> wt[576][64]
__global__ void transpose_w_kernel(const float* __restrict__ w, float* __restrict__ wt)
{
    int i = blockIdx.x * 256 + threadIdx.x;
    if (i < 64 * 576) {
        int oc = i / 576;
        int kk = i - oc * 576;
        wt[kk * 64 + oc] = w[i];
    }
}

// ---------------------------------------------------------------------------
// mma.sync tf32 implicit-GEMM 3x3 conv (3xTF32 split).
// One block = one image row: M = 128 px, N = C_OUT, K = 9*C_IN in chunks of
// (k-position, 32 ic). 8 warps = 4 M-tiles x 2 N-halves. Stride-36 smem pad
// gives conflict-free fragment loads. Output NHWC (features) or NCHW (offsets).
// ---------------------------------------------------------------------------
template <int N_OC, int C_IN, bool NHWC_OUT>
__global__ __launch_bounds__(256)
void conv_mma_kernel(const float* __restrict__ in, const float* __restrict__ wh,
                     const float* __restrict__ wl, const float* __restrict__ bias,
                     float* __restrict__ out)
{
    extern __shared__ __align__(16) float sm[];
    constexpr int KTOT = C_IN * 9;
    constexpr int ICH  = C_IN / 32;            // ic-chunks per k position
    constexpr int NCH  = ICH * 9;
    constexpr int ST   = 36;                   // smem row stride (floats)
    constexpr int A_HI = 0;
    constexpr int A_LO = A_HI + 128 * ST;
    constexpr int B_HI = A_LO + 128 * ST;
    constexpr int B_LO = B_HI + N_OC * ST;
    constexpr int NA   = N_OC / 16;            // n-atoms per warp (9 or 4)

    const int tid  = threadIdx.x;
    const int lane = tid & 31;
    const int wid  = tid >> 5;
    const int mw   = wid & 3;                  // 0..3 -> 32 px each
    const int nw   = wid >> 2;                 // 0..1 -> N_OC/2 each
    const int m0   = mw * 32;
    const int n0   = nw * (N_OC / 2);

    const int r = blockIdx.x;
    const int b = r >> 7;
    const int y = r & 127;

    float acc[2][NA][4];
#pragma unroll
    for (int m = 0; m < 2; m++)
#pragma unroll
        for (int na = 0; na < NA; na++)
#pragma unroll
            for (int q = 0; q < 4; q++) acc[m][na][q] = 0.0f;

    const int lpx = tid >> 1;                  // A-load px for this thread
    const int lcb = (tid & 1) * 16;            // A-load channel base

    for (int ch = 0; ch < NCH; ch++) {
        const int k   = ch / ICH;
        const int ich = ch % ICH;
        const int dy = k / 3 - 1;
        const int dx = k % 3 - 1;

        // ---- stage A chunk: 128 px x 32 ch (hi/lo) ----
        {
            const int yy = y + dy;
            const int xx = lpx + dx;
            const bool val = (yy >= 0) && (yy < HH) && (xx >= 0) && (xx < WW);
            const float4* src = (const float4*)(in +
                (((size_t)b * HW + (size_t)yy * WW + xx) * C_IN + ich * 32 + lcb));
#pragma unroll
            for (int j = 0; j < 4; j++) {
                float4 v = val ? src[j] : make_float4(0.f, 0.f, 0.f, 0.f);
                float4 h, l;
                h.x = cvt_tf32(v.x); l.x = cvt_tf32(v.x - h.x);
                h.y = cvt_tf32(v.y); l.y = cvt_tf32(v.y - h.y);
                h.z = cvt_tf32(v.z); l.z = cvt_tf32(v.z - h.z);
                h.w = cvt_tf32(v.w); l.w = cvt_tf32(v.w - h.w);
                int o = lpx * ST + lcb + j * 4;
                *(float4*)&sm[A_HI + o] = h;
                *(float4*)&sm[A_LO + o] = l;
            }
        }
        // ---- stage B chunk: N_OC oc x 32 ch (hi/lo, pre-split weights) ----
        for (int t = tid; t < N_OC * 8; t += 256) {
            int oc = t >> 3;
            int jq = t & 7;
            size_t g = (size_t)oc * KTOT + (size_t)k * C_IN + ich * 32 + jq * 4;
            float4 h = *(const float4*)&wh[g];
            float4 l = *(const float4*)&wl[g];
            int o = oc * ST + jq * 4;
            *(float4*)&sm[B_HI + o] = h;
            *(float4*)&sm[B_LO + o] = l;
        }
        __syncthreads();

        // ---- compute: 4 sub-chunks of K=8 ----
#pragma unroll
        for (int sub = 0; sub < 4; sub++) {
            const int colb = sub * 8 + (lane & 3);
            uint32_t ah[2][4], al[2][4];
#pragma unroll
            for (int m = 0; m < 2; m++) {
                int row = m0 + m * 16 + (lane >> 2);
                const uint32_t* AH = (const uint32_t*)&sm[A_HI];
                const uint32_t* AL = (const uint32_t*)&sm[A_LO];
                ah[m][0] = AH[row * ST + colb];
                ah[m][1] = AH[(row + 8) * ST + colb];
                ah[m][2] = AH[row * ST + colb + 4];
                ah[m][3] = AH[(row + 8) * ST + colb + 4];
                al[m][0] = AL[row * ST + colb];
                al[m][1] = AL[(row + 8) * ST + colb];
                al[m][2] = AL[row * ST + colb + 4];
                al[m][3] = AL[(row + 8) * ST + colb + 4];
            }
#pragma unroll
            for (int na = 0; na < NA; na++) {
                int nn = n0 + na * 8 + (lane >> 2);
                const uint32_t* BH = (const uint32_t*)&sm[B_HI];
                const uint32_t* BL = (const uint32_t*)&sm[B_LO];
                uint32_t bh0 = BH[nn * ST + colb];
                uint32_t bh1 = BH[nn * ST + colb + 4];
                uint32_t bl0 = BL[nn * ST + colb];
                uint32_t bl1 = BL[nn * ST + colb + 4];
#pragma unroll
                for (int m = 0; m < 2; m++) {
                    mma8(acc[m][na], ah[m], bh0, bh1);
                    mma8(acc[m][na], ah[m], bl0, bl1);
                    mma8(acc[m][na], al[m], bh0, bh1);
                }
            }
        }
        __syncthreads();
    }

    // ---- epilogue ----
#pragma unroll
    for (int m = 0; m < 2; m++) {
        int x0 = m0 + m * 16 + (lane >> 2);
#pragma unroll
        for (int na = 0; na < NA; na++) {
            int n = n0 + na * 8 + 2 * (lane & 3);
            float b0 = __ldg(&bias[n]);
            float b1 = __ldg(&bias[n + 1]);
            if (NHWC_OUT) {
                float* op0 = out + ((size_t)b * HW + (size_t)y * WW + x0) * N_OC + n;
                float* op1 = op0 + 8 * N_OC;
                *(float2*)op0 = make_float2(acc[m][na][0] + b0, acc[m][na][1] + b1);
                *(float2*)op1 = make_float2(acc[m][na][2] + b0, acc[m][na][3] + b1);
            } else {
                size_t base = (size_t)b * N_OC * HW + (size_t)y * WW + x0;
                out[base + (size_t)n * HW]           = acc[m][na][0] + b0;
                out[base + (size_t)(n + 1) * HW]     = acc[m][na][1] + b1;
                out[base + (size_t)n * HW + 8]       = acc[m][na][2] + b0;
                out[base + (size_t)(n + 1) * HW + 8] = acc[m][na][3] + b1;
            }
        }
    }
}

// ---------------------------------------------------------------------------
// Deformable conv. Gather source is NHWC64 (dg-group = 32B contiguous).
// Block: 8x8 spatial tile, 64 oc, one batch. Output NHWC64 or NCHW.
// ---------------------------------------------------------------------------
template <bool NCHW_OUT>
__global__ __launch_bounds__(256, 3)
void deform_kernel(const float* __restrict__ src, const float* __restrict__ off,
                   const float* __restrict__ wt, const float* __restrict__ bias,
                   float* __restrict__ out)
{
    __shared__ __align__(16) float s_cols[144 * 64];   // 36 KB

    const int tid = threadIdx.x;
    const int b   = blockIdx.z;
    const int bx0 = blockIdx.x * 8;
    const int by0 = blockIdx.y * 8;

    const int pxg = tid & 15;    // 16 groups of 4 px
    const int ocg = tid >> 4;    // 16 groups of 4 oc

    float acc[4][4];
#pragma unroll
    for (int o = 0; o < 4; o++)
#pragma unroll
        for (int p = 0; p < 4; p++) acc[o][p] = 0.0f;

    for (int dgc = 0; dgc < 4; dgc++) {
        for (int t = tid; t < 1152; t += 256) {
            int px   = t & 63;
            int rest = t >> 6;
            int k    = rest % 9;
            int dgl  = rest / 9;
            int dg   = dgc * 2 + dgl;

            int yy = by0 + (px >> 3);
            int xx = bx0 + (px & 7);

            int offch = (dg * 9 + k) * 2;
            size_t obase = (((size_t)b * 144 + offch) * HH + yy) * WW + xx;
            float dy = off[obase];
            float dx = off[obase + (size_t)HW];

            float py  = dy + (float)yy + (float)(k / 3 - 1);
            float pxc = dx + (float)xx + (float)(k % 3 - 1);
            float y0f = floorf(py);
            float x0f = floorf(pxc);
            float wy = py - y0f;
            float wx = pxc - x0f;
            int y0 = (int)y0f;
            int x0 = (int)x0f;

            float w00 = (1.0f - wy) * (1.0f - wx);
            float w01 = (1.0f - wy) * wx;
            float w10 = wy * (1.0f - wx);
            float w11 = wy * wx;

            bool vy0 = ((unsigned)y0 < (unsigned)HH);
            bool vy1 = ((unsigned)(y0 + 1) < (unsigned)HH);
            bool vx0 = ((unsigned)x0 < (unsigned)WW);
            bool vx1 = ((unsigned)(x0 + 1) < (unsigned)WW);
            w00 *= (float)(vy0 && vx0);
            w01 *= (float)(vy0 && vx1);
            w10 *= (float)(vy1 && vx0);
            w11 *= (float)(vy1 && vx1);

            int y0c = min(max(y0, 0), HH - 1);
            int y1c = min(max(y0 + 1, 0), HH - 1);
            int x0c = min(max(x0, 0), WW - 1);
            int x1c = min(max(x0 + 1, 0), WW - 1);

            const float* base = src + (size_t)b * HW * 64 + dg * 8;
            const float4* p00 = (const float4*)(base + (size_t)(y0c * WW + x0c) * 64);
            const float4* p01 = (const float4*)(base + (size_t)(y0c * WW + x1c) * 64);
            const float4* p10 = (const float4*)(base + (size_t)(y1c * WW + x0c) * 64);
            const float4* p11 = (const float4*)(base + (size_t)(y1c * WW + x1c) * 64);

            float4 a00 = p00[0], b00 = p00[1];
            float4 a01 = p01[0], b01 = p01[1];
            float4 a10 = p10[0], b10 = p10[1];
            float4 a11 = p11[0], b11 = p11[1];

            int colbase = dgl * (8 * 9 * 64) + k * 64 + px;
            float* sc = &s_cols[colbase];
            sc[0 * 576] = w00 * a00.x + w01 * a01.x + w10 * a10.x + w11 * a11.x;
            sc[1 * 576] = w00 * a00.y + w01 * a01.y + w10 * a10.y + w11 * a11.y;
            sc[2 * 576] = w00 * a00.z + w01 * a01.z + w10 * a10.z + w11 * a11.z;
            sc[3 * 576] = w00 * a00.w + w01 * a01.w + w10 * a10.w + w11 * a11.w;
            sc[4 * 576] = w00 * b00.x + w01 * b01.x + w10 * b10.x + w11 * b11.x;
            sc[5 * 576] = w00 * b00.y + w01 * b01.y + w10 * b10.y + w11 * b11.y;
            sc[6 * 576] = w00 * b00.z + w01 * b01.z + w10 * b10.z + w11 * b11.z;
            sc[7 * 576] = w00 * b00.w + w01 * b01.w + w10 * b10.w + w11 * b11.w;
        }
        __syncthreads();

        const int kk0 = dgc * 144;
#pragma unroll 4
        for (int kk = 0; kk < 144; kk++) {
            float4 c4 = *(const float4*)&s_cols[kk * 64 + pxg * 4];
            float4 w4 = __ldg((const float4*)&wt[(size_t)(kk0 + kk) * 64 + ocg * 4]);
            acc[0][0] += w4.x * c4.x; acc[0][1] += w4.x * c4.y;
            acc[0][2] += w4.x * c4.z; acc[0][3] += w4.x * c4.w;
            acc[1][0] += w4.y * c4.x; acc[1][1] += w4.y * c4.y;
            acc[1][2] += w4.y * c4.z; acc[1][3] += w4.y * c4.w;
            acc[2][0] += w4.z * c4.x; acc[2][1] += w4.z * c4.y;
            acc[2][2] += w4.z * c4.z; acc[2][3] += w4.z * c4.w;
            acc[3][0] += w4.w * c4.x; acc[3][1] += w4.w * c4.y;
            acc[3][2] += w4.w * c4.z; acc[3][3] += w4.w * c4.w;
        }
        __syncthreads();
    }

    float bv0 = __ldg(&bias[ocg * 4 + 0]);
    float bv1 = __ldg(&bias[ocg * 4 + 1]);
    float bv2 = __ldg(&bias[ocg * 4 + 2]);
    float bv3 = __ldg(&bias[ocg * 4 + 3]);

    if (NCHW_OUT) {
        const int y  = by0 + (pxg >> 1);
        const int x0 = bx0 + (pxg & 1) * 4;
#pragma unroll
        for (int o = 0; o < 4; o++) {
            int oc = ocg * 4 + o;
            float bv = __ldg(&bias[oc]);
            float4 rr;
            rr.x = acc[o][0] + bv; rr.y = acc[o][1] + bv;
            rr.z = acc[o][2] + bv; rr.w = acc[o][3] + bv;
            *(float4*)&out[(((size_t)b * 64 + oc) * HH + y) * WW + x0] = rr;
        }
    } else {
#pragma unroll
        for (int i = 0; i < 4; i++) {
            int px = pxg * 4 + i;
            int y = by0 + (px >> 3);
            int x = bx0 + (px & 7);
            float4 rr;
            rr.x = acc[0][i] + bv0;
            rr.y = acc[1][i] + bv1;
            rr.z = acc[2][i] + bv2;
            rr.w = acc[3][i] + bv3;
            *(float4*)&out[((size_t)b * HW + (size_t)y * WW + x) * 64 + ocg * 4] = rr;
        }
    }
}

// ---------------------------------------------------------------------------
extern "C" void kernel_launch(void* const* d_in, const int* in_sizes, int n_in,
                              void* d_out, int out_size)
{
    const float* neibor = (const float*)d_in[0];
    const float* target = (const float*)d_in[1];
    const float* cr_w   = (const float*)d_in[2];
    const float* cr_b   = (const float*)d_in[3];
    const float* off1_w = (const float*)d_in[4];
    const float* off1_b = (const float*)d_in[5];
    const float* d1_w   = (const float*)d_in[6];
    const float* d1_b   = (const float*)d_in[7];
    const float* off2_w = (const float*)d_in[8];
    const float* off2_b = (const float*)d_in[9];
    const float* d2_w   = (const float*)d_in[10];
    const float* d2_b   = (const float*)d_in[11];
    const float* off3_w = (const float*)d_in[12];
    const float* off3_b = (const float*)d_in[13];
    const float* d3_w   = (const float*)d_in[14];
    const float* d3_b   = (const float*)d_in[15];
    const float* off4_w = (const float*)d_in[16];
    const float* off4_b = (const float*)d_in[17];
    const float* d4_w   = (const float*)d_in[18];
    const float* d4_b   = (const float*)d_in[19];
    float* out = (float*)d_out;

    float *bufA, *bufB, *offb, *nhwc128, *nhwcN, *wt, *wh, *wl;
    cudaGetSymbolAddress((void**)&bufA,    g_bufA);
    cudaGetSymbolAddress((void**)&bufB,    g_bufB);
    cudaGetSymbolAddress((void**)&offb,    g_offb);
    cudaGetSymbolAddress((void**)&nhwc128, g_nhwc128);
    cudaGetSymbolAddress((void**)&nhwcN,   g_nhwcN);
    cudaGetSymbolAddress((void**)&wt,      g_wt);
    cudaGetSymbolAddress((void**)&wh,      g_wh);
    cudaGetSymbolAddress((void**)&wl,      g_wl);

    // dynamic smem: floats = 2*128*36 + 2*N_OC*36
    const int SM_CR  = (2 * 128 * 36 + 2 * 64 * 36) * 4;    // 55296
    const int SM_OFF = (2 * 128 * 36 + 2 * 144 * 36) * 4;   // 78336
    cudaFuncSetAttribute(conv_mma_kernel<64, 128, true>,
                         cudaFuncAttributeMaxDynamicSharedMemorySize, SM_CR);
    cudaFuncSetAttribute(conv_mma_kernel<144, 64, false>,
                         cudaFuncAttributeMaxDynamicSharedMemorySize, SM_OFF);

    dim3 tb(256);
    dim3 dg(WW / 8, HH / 8, NB);                // deform grid
    const int ggrid = NB * HH;                  // 512 conv-GEMM blocks
    const int tgrid = NB * HW / 256;            // transform blocks

    // input transforms (independent)
    concat_nhwc128_kernel<<<tgrid, tb>>>(neibor, target, nhwc128);
    nhwc64_kernel<<<tgrid, tb>>>(neibor, nhwcN);

    // 1. fea1 = conv_cr(concat)  -> bufA (NHWC64)
    wprep_kernel<<<(64 * 128 * 9 + 255) / 256, tb>>>(cr_w, wh, wl, 128, 64);
    conv_mma_kernel<64, 128, true><<<ggrid, tb, SM_CR>>>(nhwc128, wh, wl, cr_b, bufA);

    // 2. o1 = off1(fea1) -> offb (NCHW); fea2 = deform(fea1, o1) -> bufB
    wprep_kernel<<<(144 * 64 * 9 + 255) / 256, tb>>>(off1_w, wh, wl, 64, 144);
    conv_mma_kernel<144, 64, false><<<ggrid, tb, SM_OFF>>>(bufA, wh, wl, off1_b, offb);
    transpose_w_kernel<<<144, tb>>>(d1_w, wt);
    deform_kernel<false><<<dg, tb>>>(bufA, offb, wt, d1_b, bufB);

    // 3. o2 = off2(fea2); fea3 = deform(fea2, o2) -> bufA
    wprep_kernel<<<(144 * 64 * 9 + 255) / 256, tb>>>(off2_w, wh, wl, 64, 144);
    conv_mma_kernel<144, 64, false><<<ggrid, tb, SM_OFF>>>(bufB, wh, wl, off2_b, offb);
    transpose_w_kernel<<<144, tb>>>(d2_w, wt);
    deform_kernel<false><<<dg, tb>>>(bufB, offb, wt, d2_b, bufA);

    // 4. o3 = off3(fea3); fea4 = deform(neibor, o3) -> bufB
    wprep_kernel<<<(144 * 64 * 9 + 255) / 256, tb>>>(off3_w, wh, wl, 64, 144);
    conv_mma_kernel<144, 64, false><<<ggrid, tb, SM_OFF>>>(bufA, wh, wl, off3_b, offb);
    transpose_w_kernel<<<144, tb>>>(d3_w, wt);
    deform_kernel<false><<<dg, tb>>>(nhwcN, offb, wt, d3_b, bufB);

    // 5. o4 = off4(fea4); aligned = deform(fea4, o4) -> d_out (NCHW)
    wprep_kernel<<<(144 * 64 * 9 + 255) / 256, tb>>>(off4_w, wh, wl, 64, 144);
    conv_mma_kernel<144, 64, false><<<ggrid, tb, SM_OFF>>>(bufB, wh, wl, off4_b, offb);
    transpose_w_kernel<<<144, tb>>>(d4_w, wt);
    deform_kernel<true><<<dg, tb>>>(bufB, offb, wt, d4_b, out);
}

// round 7
// speedup vs baseline: 1.2027x; 1.2027x over previous
#include <cuda_runtime.h>
#include <cuda_bf16.h>
#include <math.h>
#include <stdint.h>

#define HH 128
#define WW 128
#define NB 4
#define HW (HH * WW)

// ---------------- scratch (static device arrays; no allocation) ------------
__device__ float g_bufA[NB * 64 * HW];      // NHWC64 feature buffer
__device__ float g_bufB[NB * 64 * HW];      // NHWC64 feature buffer
__device__ float g_offb[NB * 144 * HW];     // offsets, NCHW
__device__ float g_nhwc128[NB * 128 * HW];  // concat(neibor,target) NHWC128
__device__ float g_nhwcN[NB * 64 * HW];     // neibor NHWC64
__device__ float g_wt[576 * 64];            // deform weights transposed
__device__ uint32_t g_wph[73728];           // conv weights hi, packed bf16x2 words
__device__ uint32_t g_wpl[73728];           // conv weights lo, packed bf16x2 words

// ---------------- helpers ---------------------------------------------------
// split a float pair into packed bf16x2 hi word + lo word (k-even in low half)
__device__ __forceinline__ void split2(float v0, float v1,
                                       uint32_t& hw, uint32_t& lw) {
    __nv_bfloat16 h0 = __float2bfloat16_rn(v0);
    __nv_bfloat16 h1 = __float2bfloat16_rn(v1);
    float l0 = v0 - __bfloat162float(h0);
    float l1 = v1 - __bfloat162float(h1);
    __nv_bfloat162 hp = __halves2bfloat162(h0, h1);
    __nv_bfloat162 lp = __floats2bfloat162_rn(l0, l1);
    hw = *(uint32_t*)&hp;
    lw = *(uint32_t*)&lp;
}
__device__ __forceinline__ void mma16(float* c, const uint32_t* a,
                                      uint32_t b0, uint32_t b1) {
    asm volatile(
        "mma.sync.aligned.m16n8k16.row.col.f32.bf16.bf16.f32 "
        "{%0,%1,%2,%3}, {%4,%5,%6,%7}, {%8,%9}, {%0,%1,%2,%3};"
        : "+f"(c[0]), "+f"(c[1]), "+f"(c[2]), "+f"(c[3])
        : "r"(a[0]), "r"(a[1]), "r"(a[2]), "r"(a[3]), "r"(b0), "r"(b1));
}

// ---------------------------------------------------------------------------
// Transforms
// ---------------------------------------------------------------------------
__global__ __launch_bounds__(256) void concat_nhwc128_kernel(
    const float* __restrict__ n, const float* __restrict__ t, float* __restrict__ out)
{
    int idx = blockIdx.x * 256 + threadIdx.x;   // NB*HW
    int b  = idx >> 14;
    int yx = idx & (HW - 1);
    const float* s0 = n + (size_t)b * 64 * HW + yx;
    const float* s1 = t + (size_t)b * 64 * HW + yx;
    float* o = out + (size_t)idx * 128;
#pragma unroll 8
    for (int c = 0; c < 64; c++) o[c] = s0[(size_t)c * HW];
#pragma unroll 8
    for (int c = 0; c < 64; c++) o[64 + c] = s1[(size_t)c * HW];
}

__global__ __launch_bounds__(256) void nhwc64_kernel(
    const float* __restrict__ in, float* __restrict__ out)
{
    int idx = blockIdx.x * 256 + threadIdx.x;
    int b  = idx >> 14;
    int yx = idx & (HW - 1);
    const float* s = in + (size_t)b * 64 * HW + yx;
    float* o = out + (size_t)idx * 64;
#pragma unroll 8
    for (int c = 0; c < 64; c++) o[c] = s[(size_t)c * HW];
}

// conv weight prep: w[oc][ic][3][3] -> packed bf16x2 hi/lo words laid out as
// [chunk ch][kg][oc][8 words], ch = (kpos, ich), kg = 16-ch half of the chunk.
__global__ void wprep_kernel(const float* __restrict__ w, uint32_t* __restrict__ wph,
                             uint32_t* __restrict__ wpl, int C_IN, int C_OUT)
{
    int i = blockIdx.x * 256 + threadIdx.x;
    int tot = C_OUT * C_IN * 9 / 2;
    if (i >= tot) return;
    int wd = i & 7;
    int t  = i >> 3;
    int oc = t % C_OUT;
    int t2 = t / C_OUT;
    int kg = t2 & 1;
    int ch = t2 >> 1;
    int ICH = C_IN / 32;
    int kpos = ch / ICH;
    int ich  = ch % ICH;
    int ic = ich * 32 + kg * 16 + wd * 2;
    float v0 = w[((size_t)oc * C_IN + ic) * 9 + kpos];
    float v1 = w[((size_t)oc * C_IN + ic + 1) * 9 + kpos];
    uint32_t hw, lw;
    split2(v0, v1, hw, lw);
    wph[i] = hw;
    wpl[i] = lw;
}

// deform weights: w[64][64*9] -> wt[576][64]
__global__ void transpose_w_kernel(const float* __restrict__ w, float* __restrict__ wt)
{
    int i = blockIdx.x * 256 + threadIdx.x;
    if (i < 64 * 576) {
        int oc = i / 576;
        int kk = i - oc * 576;
        wt[kk * 64 + oc] = w[i];
    }
}

// ---------------------------------------------------------------------------
// mma.sync bf16 implicit-GEMM 3x3 conv (3xBF16 hi/lo split, m16n8k16).
// One block = one image row: M = 128 px, N = C_OUT, K = 9*C_IN in chunks of
// (k-position, 32 ic) = 2 k16 groups. 8 warps = 4 M-tiles x 2 N-halves.
// Word row stride 20 -> conflict-free fragment LDS.
// ---------------------------------------------------------------------------
template <int N_OC, int C_IN, bool NHWC_OUT>
__global__ __launch_bounds__(256)
void conv_mma_kernel(const float* __restrict__ in, const uint32_t* __restrict__ wph,
                     const uint32_t* __restrict__ wpl, const float* __restrict__ bias,
                     float* __restrict__ out)
{
    extern __shared__ __align__(16) uint32_t SM[];
    constexpr int KTOT   = C_IN * 9;
    constexpr int ICH    = C_IN / 32;          // ic-chunks per k position
    constexpr int NCH    = ICH * 9;
    constexpr int RST    = 20;                 // word row stride
    constexpr int APLANE = 128 * RST;          // one kg plane of A
    constexpr int BPLANE = N_OC * RST;
    constexpr int A_HI = 0;
    constexpr int A_LO = A_HI + 2 * APLANE;
    constexpr int B_HI = A_LO + 2 * APLANE;
    constexpr int B_LO = B_HI + 2 * BPLANE;
    constexpr int NA   = N_OC / 16;            // n-atoms per warp (9 or 4)

    const int tid  = threadIdx.x;
    const int lane = tid & 31;
    const int wid  = tid >> 5;
    const int mw   = wid & 3;                  // 0..3 -> 32 px each
    const int nw   = wid >> 2;                 // 0..1 -> N_OC/2 each
    const int m0   = mw * 32;
    const int n0   = nw * (N_OC / 2);

    const int r = blockIdx.x;
    const int b = r >> 7;
    const int y = r & 127;

    float acc[2][NA][4];
#pragma unroll
    for (int m = 0; m < 2; m++)
#pragma unroll
        for (int na = 0; na < NA; na++)
#pragma unroll
            for (int q = 0; q < 4; q++) acc[m][na][q] = 0.0f;

    const int lpx = tid >> 1;                  // A-load px for this thread
    const int lkg = tid & 1;                   // A-load kg (16-ch half)

    for (int ch = 0; ch < NCH; ch++) {
        const int k   = ch / ICH;
        const int ich = ch % ICH;
        const int dy = k / 3 - 1;
        const int dx = k % 3 - 1;

        // ---- stage A chunk: 128 px x 32 ch -> bf16 hi/lo packed words ----
        {
            const int yy = y + dy;
            const int xx = lpx + dx;
            const bool val = (yy >= 0) && (yy < HH) && (xx >= 0) && (xx < WW);
            const float4* src = (const float4*)(in +
                (((size_t)b * HW + (size_t)yy * WW + xx) * C_IN + ich * 32 + lkg * 16));
            const int abase = lkg * APLANE + lpx * RST;
#pragma unroll
            for (int j = 0; j < 4; j++) {
                float4 v = val ? src[j] : make_float4(0.f, 0.f, 0.f, 0.f);
                uint32_t h0, l0, h1, l1;
                split2(v.x, v.y, h0, l0);
                split2(v.z, v.w, h1, l1);
                *(uint2*)&SM[A_HI + abase + 2 * j] = make_uint2(h0, h1);
                *(uint2*)&SM[A_LO + abase + 2 * j] = make_uint2(l0, l1);
            }
        }
        // ---- stage B chunk: straight copy of pre-packed words ----
        for (int t = tid; t < N_OC * 16; t += 256) {
            int kg  = t / (N_OC * 8);
            int rem = t - kg * (N_OC * 8);
            int n   = rem >> 3;
            int wd  = rem & 7;
            int gsrc = ((ch * 2 + kg) * N_OC + n) * 8 + wd;
            int o = kg * BPLANE + n * RST + wd;
            SM[B_HI + o] = wph[gsrc];
            SM[B_LO + o] = wpl[gsrc];
        }
        __syncthreads();

        // ---- compute: 2 k16 groups ----
#pragma unroll
        for (int kg = 0; kg < 2; kg++) {
            const int c = lane & 3;
            const int rr = lane >> 2;
            uint32_t ah[2][4], al[2][4];
#pragma unroll
            for (int m = 0; m < 2; m++) {
                int row = m0 + m * 16 + rr;
                int ab = kg * APLANE + row * RST + c;
                ah[m][0] = SM[A_HI + ab];
                ah[m][1] = SM[A_HI + ab + 8 * RST];
                ah[m][2] = SM[A_HI + ab + 4];
                ah[m][3] = SM[A_HI + ab + 8 * RST + 4];
                al[m][0] = SM[A_LO + ab];
                al[m][1] = SM[A_LO + ab + 8 * RST];
                al[m][2] = SM[A_LO + ab + 4];
                al[m][3] = SM[A_LO + ab + 8 * RST + 4];
            }
#pragma unroll
            for (int na = 0; na < NA; na++) {
                int nn = n0 + na * 8 + rr;
                int bb = kg * BPLANE + nn * RST + c;
                uint32_t bh0 = SM[B_HI + bb];
                uint32_t bh1 = SM[B_HI + bb + 4];
                uint32_t bl0 = SM[B_LO + bb];
                uint32_t bl1 = SM[B_LO + bb + 4];
#pragma unroll
                for (int m = 0; m < 2; m++) {
                    mma16(acc[m][na], ah[m], bh0, bh1);
                    mma16(acc[m][na], ah[m], bl0, bl1);
                    mma16(acc[m][na], al[m], bh0, bh1);
                }
            }
        }
        __syncthreads();
    }

    // ---- epilogue (C fragment layout same as m16n8k8) ----
#pragma unroll
    for (int m = 0; m < 2; m++) {
        int x0 = m0 + m * 16 + (lane >> 2);
#pragma unroll
        for (int na = 0; na < NA; na++) {
            int n = n0 + na * 8 + 2 * (lane & 3);
            float b0 = __ldg(&bias[n]);
            float b1 = __ldg(&bias[n + 1]);
            if (NHWC_OUT) {
                float* op0 = out + ((size_t)b * HW + (size_t)y * WW + x0) * N_OC + n;
                float* op1 = op0 + 8 * N_OC;
                *(float2*)op0 = make_float2(acc[m][na][0] + b0, acc[m][na][1] + b1);
                *(float2*)op1 = make_float2(acc[m][na][2] + b0, acc[m][na][3] + b1);
            } else {
                size_t base = (size_t)b * N_OC * HW + (size_t)y * WW + x0;
                out[base + (size_t)n * HW]           = acc[m][na][0] + b0;
                out[base + (size_t)(n + 1) * HW]     = acc[m][na][1] + b1;
                out[base + (size_t)n * HW + 8]       = acc[m][na][2] + b0;
                out[base + (size_t)(n + 1) * HW + 8] = acc[m][na][3] + b1;
            }
        }
    }
}

// ---------------------------------------------------------------------------
// Deformable conv. Gather source is NHWC64 (dg-group = 32B contiguous).
// Block: 8x8 spatial tile, 64 oc, one batch. Output NHWC64 or NCHW.
// ---------------------------------------------------------------------------
template <bool NCHW_OUT>
__global__ __launch_bounds__(256, 3)
void deform_kernel(const float* __restrict__ src, const float* __restrict__ off,
                   const float* __restrict__ wt, const float* __restrict__ bias,
                   float* __restrict__ out)
{
    __shared__ __align__(16) float s_cols[144 * 64];   // 36 KB

    const int tid = threadIdx.x;
    const int b   = blockIdx.z;
    const int bx0 = blockIdx.x * 8;
    const int by0 = blockIdx.y * 8;

    const int pxg = tid & 15;    // 16 groups of 4 px
    const int ocg = tid >> 4;    // 16 groups of 4 oc

    float acc[4][4];
#pragma unroll
    for (int o = 0; o < 4; o++)
#pragma unroll
        for (int p = 0; p < 4; p++) acc[o][p] = 0.0f;

    for (int dgc = 0; dgc < 4; dgc++) {
        for (int t = tid; t < 1152; t += 256) {
            int px   = t & 63;
            int rest = t >> 6;
            int k    = rest % 9;
            int dgl  = rest / 9;
            int dg   = dgc * 2 + dgl;

            int yy = by0 + (px >> 3);
            int xx = bx0 + (px & 7);

            int offch = (dg * 9 + k) * 2;
            size_t obase = (((size_t)b * 144 + offch) * HH + yy) * WW + xx;
            float dy = off[obase];
            float dx = off[obase + (size_t)HW];

            float py  = dy + (float)yy + (float)(k / 3 - 1);
            float pxc = dx + (float)xx + (float)(k % 3 - 1);
            float y0f = floorf(py);
            float x0f = floorf(pxc);
            float wy = py - y0f;
            float wx = pxc - x0f;
            int y0 = (int)y0f;
            int x0 = (int)x0f;

            float w00 = (1.0f - wy) * (1.0f - wx);
            float w01 = (1.0f - wy) * wx;
            float w10 = wy * (1.0f - wx);
            float w11 = wy * wx;

            bool vy0 = ((unsigned)y0 < (unsigned)HH);
            bool vy1 = ((unsigned)(y0 + 1) < (unsigned)HH);
            bool vx0 = ((unsigned)x0 < (unsigned)WW);
            bool vx1 = ((unsigned)(x0 + 1) < (unsigned)WW);
            w00 *= (float)(vy0 && vx0);
            w01 *= (float)(vy0 && vx1);
            w10 *= (float)(vy1 && vx0);
            w11 *= (float)(vy1 && vx1);

            int y0c = min(max(y0, 0), HH - 1);
            int y1c = min(max(y0 + 1, 0), HH - 1);
            int x0c = min(max(x0, 0), WW - 1);
            int x1c = min(max(x0 + 1, 0), WW - 1);

            const float* base = src + (size_t)b * HW * 64 + dg * 8;
            const float4* p00 = (const float4*)(base + (size_t)(y0c * WW + x0c) * 64);
            const float4* p01 = (const float4*)(base + (size_t)(y0c * WW + x1c) * 64);
            const float4* p10 = (const float4*)(base + (size_t)(y1c * WW + x0c) * 64);
            const float4* p11 = (const float4*)(base + (size_t)(y1c * WW + x1c) * 64);

            float4 a00 = p00[0], b00 = p00[1];
            float4 a01 = p01[0], b01 = p01[1];
            float4 a10 = p10[0], b10 = p10[1];
            float4 a11 = p11[0], b11 = p11[1];

            int colbase = dgl * (8 * 9 * 64) + k * 64 + px;
            float* sc = &s_cols[colbase];
            sc[0 * 576] = w00 * a00.x + w01 * a01.x + w10 * a10.x + w11 * a11.x;
            sc[1 * 576] = w00 * a00.y + w01 * a01.y + w10 * a10.y + w11 * a11.y;
            sc[2 * 576] = w00 * a00.z + w01 * a01.z + w10 * a10.z + w11 * a11.z;
            sc[3 * 576] = w00 * a00.w + w01 * a01.w + w10 * a10.w + w11 * a11.w;
            sc[4 * 576] = w00 * b00.x + w01 * b01.x + w10 * b10.x + w11 * b11.x;
            sc[5 * 576] = w00 * b00.y + w01 * b01.y + w10 * b10.y + w11 * b11.y;
            sc[6 * 576] = w00 * b00.z + w01 * b01.z + w10 * b10.z + w11 * b11.z;
            sc[7 * 576] = w00 * b00.w + w01 * b01.w + w10 * b10.w + w11 * b11.w;
        }
        __syncthreads();

        const int kk0 = dgc * 144;
#pragma unroll 4
        for (int kk = 0; kk < 144; kk++) {
            float4 c4 = *(const float4*)&s_cols[kk * 64 + pxg * 4];
            float4 w4 = __ldg((const float4*)&wt[(size_t)(kk0 + kk) * 64 + ocg * 4]);
            acc[0][0] += w4.x * c4.x; acc[0][1] += w4.x * c4.y;
            acc[0][2] += w4.x * c4.z; acc[0][3] += w4.x * c4.w;
            acc[1][0] += w4.y * c4.x; acc[1][1] += w4.y * c4.y;
            acc[1][2] += w4.y * c4.z; acc[1][3] += w4.y * c4.w;
            acc[2][0] += w4.z * c4.x; acc[2][1] += w4.z * c4.y;
            acc[2][2] += w4.z * c4.z; acc[2][3] += w4.z * c4.w;
            acc[3][0] += w4.w * c4.x; acc[3][1] += w4.w * c4.y;
            acc[3][2] += w4.w * c4.z; acc[3][3] += w4.w * c4.w;
        }
        __syncthreads();
    }

    float bv0 = __ldg(&bias[ocg * 4 + 0]);
    float bv1 = __ldg(&bias[ocg * 4 + 1]);
    float bv2 = __ldg(&bias[ocg * 4 + 2]);
    float bv3 = __ldg(&bias[ocg * 4 + 3]);

    if (NCHW_OUT) {
        const int y  = by0 + (pxg >> 1);
        const int x0 = bx0 + (pxg & 1) * 4;
#pragma unroll
        for (int o = 0; o < 4; o++) {
            int oc = ocg * 4 + o;
            float bv = __ldg(&bias[oc]);
            float4 rr;
            rr.x = acc[o][0] + bv; rr.y = acc[o][1] + bv;
            rr.z = acc[o][2] + bv; rr.w = acc[o][3] + bv;
            *(float4*)&out[(((size_t)b * 64 + oc) * HH + y) * WW + x0] = rr;
        }
    } else {
#pragma unroll
        for (int i = 0; i < 4; i++) {
            int px = pxg * 4 + i;
            int y = by0 + (px >> 3);
            int x = bx0 + (px & 7);
            float4 rr;
            rr.x = acc[0][i] + bv0;
            rr.y = acc[1][i] + bv1;
            rr.z = acc[2][i] + bv2;
            rr.w = acc[3][i] + bv3;
            *(float4*)&out[((size_t)b * HW + (size_t)y * WW + x) * 64 + ocg * 4] = rr;
        }
    }
}

// ---------------------------------------------------------------------------
extern "C" void kernel_launch(void* const* d_in, const int* in_sizes, int n_in,
                              void* d_out, int out_size)
{
    const float* neibor = (const float*)d_in[0];
    const float* target = (const float*)d_in[1];
    const float* cr_w   = (const float*)d_in[2];
    const float* cr_b   = (const float*)d_in[3];
    const float* off1_w = (const float*)d_in[4];
    const float* off1_b = (const float*)d_in[5];
    const float* d1_w   = (const float*)d_in[6];
    const float* d1_b   = (const float*)d_in[7];
    const float* off2_w = (const float*)d_in[8];
    const float* off2_b = (const float*)d_in[9];
    const float* d2_w   = (const float*)d_in[10];
    const float* d2_b   = (const float*)d_in[11];
    const float* off3_w = (const float*)d_in[12];
    const float* off3_b = (const float*)d_in[13];
    const float* d3_w   = (const float*)d_in[14];
    const float* d3_b   = (const float*)d_in[15];
    const float* off4_w = (const float*)d_in[16];
    const float* off4_b = (const float*)d_in[17];
    const float* d4_w   = (const float*)d_in[18];
    const float* d4_b   = (const float*)d_in[19];
    float* out = (float*)d_out;

    float *bufA, *bufB, *offb, *nhwc128, *nhwcN, *wt;
    uint32_t *wph, *wpl;
    cudaGetSymbolAddress((void**)&bufA,    g_bufA);
    cudaGetSymbolAddress((void**)&bufB,    g_bufB);
    cudaGetSymbolAddress((void**)&offb,    g_offb);
    cudaGetSymbolAddress((void**)&nhwc128, g_nhwc128);
    cudaGetSymbolAddress((void**)&nhwcN,   g_nhwcN);
    cudaGetSymbolAddress((void**)&wt,      g_wt);
    cudaGetSymbolAddress((void**)&wph,     g_wph);
    cudaGetSymbolAddress((void**)&wpl,     g_wpl);

    // dynamic smem (bytes): (4*APLANE + 4*BPLANE) words * 4
    const int SM_CR  = (4 * 128 * 20 + 4 * 64 * 20) * 4;    // 61440
    const int SM_OFF = (4 * 128 * 20 + 4 * 144 * 20) * 4;   // 87040
    cudaFuncSetAttribute(conv_mma_kernel<64, 128, true>,
                         cudaFuncAttributeMaxDynamicSharedMemorySize, SM_CR);
    cudaFuncSetAttribute(conv_mma_kernel<144, 64, false>,
                         cudaFuncAttributeMaxDynamicSharedMemorySize, SM_OFF);

    dim3 tb(256);
    dim3 dg(WW / 8, HH / 8, NB);                // deform grid
    const int ggrid = NB * HH;                  // 512 conv-GEMM blocks
    const int tgrid = NB * HW / 256;            // transform blocks
    const int WPREP_CR  = (64 * 1152 / 2 + 255) / 256;
    const int WPREP_OFF = (144 * 576 / 2 + 255) / 256;

    // input transforms (independent)
    concat_nhwc128_kernel<<<tgrid, tb>>>(neibor, target, nhwc128);
    nhwc64_kernel<<<tgrid, tb>>>(neibor, nhwcN);

    // 1. fea1 = conv_cr(concat)  -> bufA (NHWC64)
    wprep_kernel<<<WPREP_CR, tb>>>(cr_w, wph, wpl, 128, 64);
    conv_mma_kernel<64, 128, true><<<ggrid, tb, SM_CR>>>(nhwc128, wph, wpl, cr_b, bufA);

    // 2. o1 = off1(fea1) -> offb (NCHW); fea2 = deform(fea1, o1) -> bufB
    wprep_kernel<<<WPREP_OFF, tb>>>(off1_w, wph, wpl, 64, 144);
    conv_mma_kernel<144, 64, false><<<ggrid, tb, SM_OFF>>>(bufA, wph, wpl, off1_b, offb);
    transpose_w_kernel<<<144, tb>>>(d1_w, wt);
    deform_kernel<false><<<dg, tb>>>(bufA, offb, wt, d1_b, bufB);

    // 3. o2 = off2(fea2); fea3 = deform(fea2, o2) -> bufA
    wprep_kernel<<<WPREP_OFF, tb>>>(off2_w, wph, wpl, 64, 144);
    conv_mma_kernel<144, 64, false><<<ggrid, tb, SM_OFF>>>(bufB, wph, wpl, off2_b, offb);
    transpose_w_kernel<<<144, tb>>>(d2_w, wt);
    deform_kernel<false><<<dg, tb>>>(bufB, offb, wt, d2_b, bufA);

    // 4. o3 = off3(fea3); fea4 = deform(neibor, o3) -> bufB
    wprep_kernel<<<WPREP_OFF, tb>>>(off3_w, wph, wpl, 64, 144);
    conv_mma_kernel<144, 64, false><<<ggrid, tb, SM_OFF>>>(bufA, wph, wpl, off3_b, offb);
    transpose_w_kernel<<<144, tb>>>(d3_w, wt);
    deform_kernel<false><<<dg, tb>>>(nhwcN, offb, wt, d3_b, bufB);

    // 5. o4 = off4(fea4); aligned = deform(fea4, o4) -> d_out (NCHW)
    wprep_kernel<<<WPREP_OFF, tb>>>(off4_w, wph, wpl, 64, 144);
    conv_mma_kernel<144, 64, false><<<ggrid, tb, SM_OFF>>>(bufB, wph, wpl, off4_b, offb);
    transpose_w_kernel<<<144, tb>>>(d4_w, wt);
    deform_kernel<true><<<dg, tb>>>(bufB, offb, wt, d4_b, out);
}

// round 9
// speedup vs baseline: 1.5265x; 1.2693x over previous
#include <cuda_runtime.h>
#include <cuda_bf16.h>
#include <math.h>
#include <stdint.h>

#define HH 128
#define WW 128
#define NB 4
#define HW (HH * WW)

// ---------------- scratch (static device arrays; no allocation) ------------
__device__ float g_bufA[NB * 64 * HW];      // NHWC64 feature buffer
__device__ float g_bufB[NB * 64 * HW];      // NHWC64 feature buffer
__device__ float g_offb[NB * 144 * HW];     // offsets, NCHW
__device__ float g_nhwc128[NB * 128 * HW];  // concat(neibor,target) NHWC128
__device__ float g_nhwcN[NB * 64 * HW];     // neibor NHWC64
__device__ uint32_t g_wph[73728];           // conv weights hi, packed bf16x2 words
__device__ uint32_t g_wpl[73728];           // conv weights lo, packed bf16x2 words
__device__ uint32_t g_dwph[18432];          // deform weights hi, packed
__device__ uint32_t g_dwpl[18432];          // deform weights lo, packed

// ---------------- helpers ---------------------------------------------------
// split a float pair into packed bf16x2 hi word + lo word (even elem low half)
__device__ __forceinline__ void split2(float v0, float v1,
                                       uint32_t& hw, uint32_t& lw) {
    __nv_bfloat16 h0 = __float2bfloat16_rn(v0);
    __nv_bfloat16 h1 = __float2bfloat16_rn(v1);
    float l0 = v0 - __bfloat162float(h0);
    float l1 = v1 - __bfloat162float(h1);
    __nv_bfloat162 hp = __halves2bfloat162(h0, h1);
    __nv_bfloat162 lp = __floats2bfloat162_rn(l0, l1);
    hw = *(uint32_t*)&hp;
    lw = *(uint32_t*)&lp;
}
__device__ __forceinline__ void mma16(float* c, const uint32_t* a,
                                      uint32_t b0, uint32_t b1) {
    asm volatile(
        "mma.sync.aligned.m16n8k16.row.col.f32.bf16.bf16.f32 "
        "{%0,%1,%2,%3}, {%4,%5,%6,%7}, {%8,%9}, {%0,%1,%2,%3};"
        : "+f"(c[0]), "+f"(c[1]), "+f"(c[2]), "+f"(c[3])
        : "r"(a[0]), "r"(a[1]), "r"(a[2]), "r"(a[3]), "r"(b0), "r"(b1));
}

// ---------------------------------------------------------------------------
// Transforms
// ---------------------------------------------------------------------------
__global__ __launch_bounds__(256) void concat_nhwc128_kernel(
    const float* __restrict__ n, const float* __restrict__ t, float* __restrict__ out)
{
    int idx = blockIdx.x * 256 + threadIdx.x;   // NB*HW
    int b  = idx >> 14;
    int yx = idx & (HW - 1);
    const float* s0 = n + (size_t)b * 64 * HW + yx;
    const float* s1 = t + (size_t)b * 64 * HW + yx;
    float* o = out + (size_t)idx * 128;
#pragma unroll 8
    for (int c = 0; c < 64; c++) o[c] = s0[(size_t)c * HW];
#pragma unroll 8
    for (int c = 0; c < 64; c++) o[64 + c] = s1[(size_t)c * HW];
}

__global__ __launch_bounds__(256) void nhwc64_kernel(
    const float* __restrict__ in, float* __restrict__ out)
{
    int idx = blockIdx.x * 256 + threadIdx.x;
    int b  = idx >> 14;
    int yx = idx & (HW - 1);
    const float* s = in + (size_t)b * 64 * HW + yx;
    float* o = out + (size_t)idx * 64;
#pragma unroll 8
    for (int c = 0; c < 64; c++) o[c] = s[(size_t)c * HW];
}

// conv weight prep: w[oc][ic][3][3] -> packed bf16x2 hi/lo words laid out as
// [chunk ch][kg][oc][8 words], ch = (kpos, ich), kg = 16-ch half of the chunk.
__global__ void wprep_kernel(const float* __restrict__ w, uint32_t* __restrict__ wph,
                             uint32_t* __restrict__ wpl, int C_IN, int C_OUT)
{
    int i = blockIdx.x * 256 + threadIdx.x;
    int tot = C_OUT * C_IN * 9 / 2;
    if (i >= tot) return;
    int wd = i & 7;
    int t  = i >> 3;
    int oc = t % C_OUT;
    int t2 = t / C_OUT;
    int kg = t2 & 1;
    int ch = t2 >> 1;
    int ICH = C_IN / 32;
    int kpos = ch / ICH;
    int ich  = ch % ICH;
    int ic = ich * 32 + kg * 16 + wd * 2;
    float v0 = w[((size_t)oc * C_IN + ic) * 9 + kpos];
    float v1 = w[((size_t)oc * C_IN + ic + 1) * 9 + kpos];
    uint32_t hw, lw;
    split2(v0, v1, hw, lw);
    wph[i] = hw;
    wpl[i] = lw;
}

// deform weight prep: w[oc][ic][9] -> packed words [(dgc*72 + wdx)*64 + oc]
// where wdx = dgl*36 + k*4 + wp and the pair is channels (wp*2, wp*2+1) of
// deform group dg = dgc*2 + dgl.
__global__ void dwprep_kernel(const float* __restrict__ w, uint32_t* __restrict__ dwph,
                              uint32_t* __restrict__ dwpl)
{
    int i = blockIdx.x * 256 + threadIdx.x;
    if (i >= 4 * 72 * 64) return;
    int oc  = i & 63;
    int t   = i >> 6;
    int wdx = t % 72;
    int dgc = t / 72;
    int dgl = wdx / 36;
    int rem = wdx % 36;
    int k   = rem >> 2;
    int wp  = rem & 3;
    int ic0 = (dgc * 2 + dgl) * 8 + wp * 2;
    float v0 = w[((size_t)oc * 64 + ic0) * 9 + k];
    float v1 = w[((size_t)oc * 64 + ic0 + 1) * 9 + k];
    uint32_t hw, lw;
    split2(v0, v1, hw, lw);
    dwph[i] = hw;
    dwpl[i] = lw;
}

// ---------------------------------------------------------------------------
// mma.sync bf16 implicit-GEMM 3x3 conv (3xBF16 hi/lo split, m16n8k16).
// ---------------------------------------------------------------------------
template <int N_OC, int C_IN, bool NHWC_OUT>
__global__ __launch_bounds__(256)
void conv_mma_kernel(const float* __restrict__ in, const uint32_t* __restrict__ wph,
                     const uint32_t* __restrict__ wpl, const float* __restrict__ bias,
                     float* __restrict__ out)
{
    extern __shared__ __align__(16) uint32_t SM[];
    constexpr int ICH    = C_IN / 32;          // ic-chunks per k position
    constexpr int NCH    = ICH * 9;
    constexpr int RST    = 20;                 // word row stride
    constexpr int APLANE = 128 * RST;          // one kg plane of A
    constexpr int BPLANE = N_OC * RST;
    constexpr int A_HI = 0;
    constexpr int A_LO = A_HI + 2 * APLANE;
    constexpr int B_HI = A_LO + 2 * APLANE;
    constexpr int B_LO = B_HI + 2 * BPLANE;
    constexpr int NA   = N_OC / 16;            // n-atoms per warp (9 or 4)

    const int tid  = threadIdx.x;
    const int lane = tid & 31;
    const int wid  = tid >> 5;
    const int mw   = wid & 3;                  // 0..3 -> 32 px each
    const int nw   = wid >> 2;                 // 0..1 -> N_OC/2 each
    const int m0   = mw * 32;
    const int n0   = nw * (N_OC / 2);

    const int r = blockIdx.x;
    const int b = r >> 7;
    const int y = r & 127;

    float acc[2][NA][4];
#pragma unroll
    for (int m = 0; m < 2; m++)
#pragma unroll
        for (int na = 0; na < NA; na++)
#pragma unroll
            for (int q = 0; q < 4; q++) acc[m][na][q] = 0.0f;

    const int lpx = tid >> 1;                  // A-load px for this thread
    const int lkg = tid & 1;                   // A-load kg (16-ch half)

    for (int ch = 0; ch < NCH; ch++) {
        const int k   = ch / ICH;
        const int ich = ch % ICH;
        const int dy = k / 3 - 1;
        const int dx = k % 3 - 1;

        // ---- stage A chunk: 128 px x 32 ch -> bf16 hi/lo packed words ----
        {
            const int yy = y + dy;
            const int xx = lpx + dx;
            const bool val = (yy >= 0) && (yy < HH) && (xx >= 0) && (xx < WW);
            const float4* src = (const float4*)(in +
                (((size_t)b * HW + (size_t)yy * WW + xx) * C_IN + ich * 32 + lkg * 16));
            const int abase = lkg * APLANE + lpx * RST;
#pragma unroll
            for (int j = 0; j < 4; j++) {
                float4 v = val ? src[j] : make_float4(0.f, 0.f, 0.f, 0.f);
                uint32_t h0, l0, h1, l1;
                split2(v.x, v.y, h0, l0);
                split2(v.z, v.w, h1, l1);
                *(uint2*)&SM[A_HI + abase + 2 * j] = make_uint2(h0, h1);
                *(uint2*)&SM[A_LO + abase + 2 * j] = make_uint2(l0, l1);
            }
        }
        // ---- stage B chunk: straight copy of pre-packed words ----
        for (int t = tid; t < N_OC * 16; t += 256) {
            int kg  = t / (N_OC * 8);
            int rem = t - kg * (N_OC * 8);
            int n   = rem >> 3;
            int wd  = rem & 7;
            int gsrc = ((ch * 2 + kg) * N_OC + n) * 8 + wd;
            int o = kg * BPLANE + n * RST + wd;
            SM[B_HI + o] = wph[gsrc];
            SM[B_LO + o] = wpl[gsrc];
        }
        __syncthreads();

        // ---- compute: 2 k16 groups ----
#pragma unroll
        for (int kg = 0; kg < 2; kg++) {
            const int c = lane & 3;
            const int rr = lane >> 2;
            uint32_t ah[2][4], al[2][4];
#pragma unroll
            for (int m = 0; m < 2; m++) {
                int row = m0 + m * 16 + rr;
                int ab = kg * APLANE + row * RST + c;
                ah[m][0] = SM[A_HI + ab];
                ah[m][1] = SM[A_HI + ab + 8 * RST];
                ah[m][2] = SM[A_HI + ab + 4];
                ah[m][3] = SM[A_HI + ab + 8 * RST + 4];
                al[m][0] = SM[A_LO + ab];
                al[m][1] = SM[A_LO + ab + 8 * RST];
                al[m][2] = SM[A_LO + ab + 4];
                al[m][3] = SM[A_LO + ab + 8 * RST + 4];
            }
#pragma unroll
            for (int na = 0; na < NA; na++) {
                int nn = n0 + na * 8 + rr;
                int bb = kg * BPLANE + nn * RST + c;
                uint32_t bh0 = SM[B_HI + bb];
                uint32_t bh1 = SM[B_HI + bb + 4];
                uint32_t bl0 = SM[B_LO + bb];
                uint32_t bl1 = SM[B_LO + bb + 4];
#pragma unroll
                for (int m = 0; m < 2; m++) {
                    mma16(acc[m][na], ah[m], bh0, bh1);
                    mma16(acc[m][na], ah[m], bl0, bl1);
                    mma16(acc[m][na], al[m], bh0, bh1);
                }
            }
        }
        __syncthreads();
    }

    // ---- epilogue ----
#pragma unroll
    for (int m = 0; m < 2; m++) {
        int x0 = m0 + m * 16 + (lane >> 2);
#pragma unroll
        for (int na = 0; na < NA; na++) {
            int n = n0 + na * 8 + 2 * (lane & 3);
            float b0 = __ldg(&bias[n]);
            float b1 = __ldg(&bias[n + 1]);
            if (NHWC_OUT) {
                float* op0 = out + ((size_t)b * HW + (size_t)y * WW + x0) * N_OC + n;
                float* op1 = op0 + 8 * N_OC;
                *(float2*)op0 = make_float2(acc[m][na][0] + b0, acc[m][na][1] + b1);
                *(float2*)op1 = make_float2(acc[m][na][2] + b0, acc[m][na][3] + b1);
            } else {
                size_t base = (size_t)b * N_OC * HW + (size_t)y * WW + x0;
                out[base + (size_t)n * HW]           = acc[m][na][0] + b0;
                out[base + (size_t)(n + 1) * HW]     = acc[m][na][1] + b1;
                out[base + (size_t)n * HW + 8]       = acc[m][na][2] + b0;
                out[base + (size_t)(n + 1) * HW + 8] = acc[m][na][3] + b1;
            }
        }
    }
}

// ---------------------------------------------------------------------------
// Deformable conv: fp32 bilinear gather (NHWC64 source) -> bf16 hi/lo cols in
// smem -> m16n8k16 MMA GEMM (3-term split). Block: 64 px (8x8), 64 oc, one b.
// A layout: [w][px] rows of 72 (64 px + 8 pad) -> conflict-free stores & frags.
// B layout: [w][oc] rows of 72. 4 dgc chunks of K=144 (9 k16 groups each).
// ---------------------------------------------------------------------------
template <bool NCHW_OUT>
__global__ __launch_bounds__(256)
void deform_kernel(const float* __restrict__ src, const float* __restrict__ off,
                   const uint32_t* __restrict__ dwph, const uint32_t* __restrict__ dwpl,
                   const float* __restrict__ bias, float* __restrict__ out)
{
    extern __shared__ __align__(16) uint32_t SM[];
    constexpr int RST   = 72;                 // padded row length (64 + 8)
    constexpr int PLANE = 72 * RST;           // 72 w-rows
    constexpr int A_HI = 0;
    constexpr int A_LO = A_HI + PLANE;
    constexpr int B_HI = A_LO + PLANE;
    constexpr int B_LO = B_HI + PLANE;

    const int tid  = threadIdx.x;
    const int lane = tid & 31;
    const int wid  = tid >> 5;
    const int m0   = (wid & 3) * 16;          // 4 m-tiles of 16 px
    const int n0   = (wid >> 2) * 32;         // 2 n-halves of 32 oc

    const int b   = blockIdx.z;
    const int bx0 = blockIdx.x * 8;
    const int by0 = blockIdx.y * 8;

    float acc[4][4];
#pragma unroll
    for (int na = 0; na < 4; na++)
#pragma unroll
        for (int q = 0; q < 4; q++) acc[na][q] = 0.0f;

    for (int dgc = 0; dgc < 4; dgc++) {
        // ---- stage B: coalesced copy of pre-packed weights ----
        for (int t = tid; t < 72 * 64; t += 256) {
            int w  = t >> 6;
            int oc = t & 63;
            int g  = ((dgc * 72 + w) << 6) + oc;
            int o  = w * RST + oc;
            SM[B_HI + o] = dwph[g];
            SM[B_LO + o] = dwpl[g];
        }
        // ---- stage A: bilinear gather + bf16 split ----
        for (int t = tid; t < 1152; t += 256) {
            int px   = t & 63;
            int rest = t >> 6;          // 0..17
            int k    = rest % 9;
            int dgl  = rest / 9;        // 0..1
            int dg   = dgc * 2 + dgl;

            int yy = by0 + (px >> 3);
            int xx = bx0 + (px & 7);

            int offch = (dg * 9 + k) * 2;
            size_t obase = (((size_t)b * 144 + offch) * HH + yy) * WW + xx;
            float dy = off[obase];
            float dx = off[obase + (size_t)HW];

            float py  = dy + (float)yy + (float)(k / 3 - 1);
            float pxc = dx + (float)xx + (float)(k % 3 - 1);
            float y0f = floorf(py);
            float x0f = floorf(pxc);
            float wy = py - y0f;
            float wx = pxc - x0f;
            int y0 = (int)y0f;
            int x0 = (int)x0f;

            float w00 = (1.0f - wy) * (1.0f - wx);
            float w01 = (1.0f - wy) * wx;
            float w10 = wy * (1.0f - wx);
            float w11 = wy * wx;

            bool vy0 = ((unsigned)y0 < (unsigned)HH);
            bool vy1 = ((unsigned)(y0 + 1) < (unsigned)HH);
            bool vx0 = ((unsigned)x0 < (unsigned)WW);
            bool vx1 = ((unsigned)(x0 + 1) < (unsigned)WW);
            w00 *= (float)(vy0 && vx0);
            w01 *= (float)(vy0 && vx1);
            w10 *= (float)(vy1 && vx0);
            w11 *= (float)(vy1 && vx1);

            int y0c = min(max(y0, 0), HH - 1);
            int y1c = min(max(y0 + 1, 0), HH - 1);
            int x0c = min(max(x0, 0), WW - 1);
            int x1c = min(max(x0 + 1, 0), WW - 1);

            const float* base = src + (size_t)b * HW * 64 + dg * 8;
            const float4* p00 = (const float4*)(base + (size_t)(y0c * WW + x0c) * 64);
            const float4* p01 = (const float4*)(base + (size_t)(y0c * WW + x1c) * 64);
            const float4* p10 = (const float4*)(base + (size_t)(y1c * WW + x0c) * 64);
            const float4* p11 = (const float4*)(base + (size_t)(y1c * WW + x1c) * 64);

            float4 a00 = p00[0], b00 = p00[1];
            float4 a01 = p01[0], b01 = p01[1];
            float4 a10 = p10[0], b10 = p10[1];
            float4 a11 = p11[0], b11 = p11[1];

            float v0 = w00 * a00.x + w01 * a01.x + w10 * a10.x + w11 * a11.x;
            float v1 = w00 * a00.y + w01 * a01.y + w10 * a10.y + w11 * a11.y;
            float v2 = w00 * a00.z + w01 * a01.z + w10 * a10.z + w11 * a11.z;
            float v3 = w00 * a00.w + w01 * a01.w + w10 * a10.w + w11 * a11.w;
            float v4 = w00 * b00.x + w01 * b01.x + w10 * b10.x + w11 * b11.x;
            float v5 = w00 * b00.y + w01 * b01.y + w10 * b10.y + w11 * b11.y;
            float v6 = w00 * b00.z + w01 * b01.z + w10 * b10.z + w11 * b11.z;
            float v7 = w00 * b00.w + w01 * b01.w + w10 * b10.w + w11 * b11.w;

            int w0 = dgl * 36 + k * 4;       // word row base
            uint32_t h, l;
            split2(v0, v1, h, l);
            SM[A_HI + (w0 + 0) * RST + px] = h;
            SM[A_LO + (w0 + 0) * RST + px] = l;
            split2(v2, v3, h, l);
            SM[A_HI + (w0 + 1) * RST + px] = h;
            SM[A_LO + (w0 + 1) * RST + px] = l;
            split2(v4, v5, h, l);
            SM[A_HI + (w0 + 2) * RST + px] = h;
            SM[A_LO + (w0 + 2) * RST + px] = l;
            split2(v6, v7, h, l);
            SM[A_HI + (w0 + 3) * RST + px] = h;
            SM[A_LO + (w0 + 3) * RST + px] = l;
        }
        __syncthreads();

        // ---- compute: 9 k16 groups of this 144-K chunk ----
        const int rr = lane >> 2;
        const int c  = lane & 3;
#pragma unroll
        for (int g = 0; g < 9; g++) {
            int wA0 = (g * 8 + c) * RST;
            int wA1 = (g * 8 + c + 4) * RST;
            int row0 = m0 + rr;
            int row1 = m0 + rr + 8;
            uint32_t ah[4], al[4];
            ah[0] = SM[A_HI + wA0 + row0];
            ah[1] = SM[A_HI + wA0 + row1];
            ah[2] = SM[A_HI + wA1 + row0];
            ah[3] = SM[A_HI + wA1 + row1];
            al[0] = SM[A_LO + wA0 + row0];
            al[1] = SM[A_LO + wA0 + row1];
            al[2] = SM[A_LO + wA1 + row0];
            al[3] = SM[A_LO + wA1 + row1];
#pragma unroll
            for (int na = 0; na < 4; na++) {
                int nn = n0 + na * 8 + rr;
                uint32_t bh0 = SM[B_HI + wA0 + nn];
                uint32_t bh1 = SM[B_HI + wA1 + nn];
                uint32_t bl0 = SM[B_LO + wA0 + nn];
                uint32_t bl1 = SM[B_LO + wA1 + nn];
                mma16(acc[na], ah, bh0, bh1);
                mma16(acc[na], ah, bl0, bl1);
                mma16(acc[na], al, bh0, bh1);
            }
        }
        __syncthreads();
    }

    // ---- epilogue ----
    const int rr = lane >> 2;
    const int c  = lane & 3;
#pragma unroll
    for (int na = 0; na < 4; na++) {
        int n = n0 + na * 8 + 2 * c;
        float b0 = __ldg(&bias[n]);
        float b1 = __ldg(&bias[n + 1]);
#pragma unroll
        for (int h = 0; h < 2; h++) {
            int px = m0 + rr + h * 8;
            int y = by0 + (px >> 3);
            int x = bx0 + (px & 7);
            float r0 = acc[na][h * 2 + 0] + b0;
            float r1 = acc[na][h * 2 + 1] + b1;
            if (NCHW_OUT) {
                size_t base = ((size_t)b * 64) * HW + (size_t)y * WW + x;
                out[base + (size_t)n * HW]       = r0;
                out[base + (size_t)(n + 1) * HW] = r1;
            } else {
                *(float2*)&out[((size_t)b * HW + (size_t)y * WW + x) * 64 + n] =
                    make_float2(r0, r1);
            }
        }
    }
}

// ---------------------------------------------------------------------------
extern "C" void kernel_launch(void* const* d_in, const int* in_sizes, int n_in,
                              void* d_out, int out_size)
{
    const float* neibor = (const float*)d_in[0];
    const float* target = (const float*)d_in[1];
    const float* cr_w   = (const float*)d_in[2];
    const float* cr_b   = (const float*)d_in[3];
    const float* off1_w = (const float*)d_in[4];
    const float* off1_b = (const float*)d_in[5];
    const float* d1_w   = (const float*)d_in[6];
    const float* d1_b   = (const float*)d_in[7];
    const float* off2_w = (const float*)d_in[8];
    const float* off2_b = (const float*)d_in[9];
    const float* d2_w   = (const float*)d_in[10];
    const float* d2_b   = (const float*)d_in[11];
    const float* off3_w = (const float*)d_in[12];
    const float* off3_b = (const float*)d_in[13];
    const float* d3_w   = (const float*)d_in[14];
    const float* d3_b   = (const float*)d_in[15];
    const float* off4_w = (const float*)d_in[16];
    const float* off4_b = (const float*)d_in[17];
    const float* d4_w   = (const float*)d_in[18];
    const float* d4_b   = (const float*)d_in[19];
    float* out = (float*)d_out;

    float *bufA, *bufB, *offb, *nhwc128, *nhwcN;
    uint32_t *wph, *wpl, *dwph, *dwpl;
    cudaGetSymbolAddress((void**)&bufA,    g_bufA);
    cudaGetSymbolAddress((void**)&bufB,    g_bufB);
    cudaGetSymbolAddress((void**)&offb,    g_offb);
    cudaGetSymbolAddress((void**)&nhwc128, g_nhwc128);
    cudaGetSymbolAddress((void**)&nhwcN,   g_nhwcN);
    cudaGetSymbolAddress((void**)&wph,     g_wph);
    cudaGetSymbolAddress((void**)&wpl,     g_wpl);
    cudaGetSymbolAddress((void**)&dwph,    g_dwph);
    cudaGetSymbolAddress((void**)&dwpl,    g_dwpl);

    const int SM_CR  = (4 * 128 * 20 + 4 * 64 * 20) * 4;    // 61440
    const int SM_OFF = (4 * 128 * 20 + 4 * 144 * 20) * 4;   // 87040
    const int SM_DEF = 4 * 72 * 72 * 4;                     // 82944
    cudaFuncSetAttribute(conv_mma_kernel<64, 128, true>,
                         cudaFuncAttributeMaxDynamicSharedMemorySize, SM_CR);
    cudaFuncSetAttribute(conv_mma_kernel<144, 64, false>,
                         cudaFuncAttributeMaxDynamicSharedMemorySize, SM_OFF);
    cudaFuncSetAttribute(deform_kernel<false>,
                         cudaFuncAttributeMaxDynamicSharedMemorySize, SM_DEF);
    cudaFuncSetAttribute(deform_kernel<true>,
                         cudaFuncAttributeMaxDynamicSharedMemorySize, SM_DEF);

    dim3 tb(256);
    dim3 dg(WW / 8, HH / 8, NB);                // deform grid
    const int ggrid = NB * HH;                  // 512 conv-GEMM blocks
    const int tgrid = NB * HW / 256;            // transform blocks
    const int WPREP_CR  = (64 * 1152 / 2 + 255) / 256;
    const int WPREP_OFF = (144 * 576 / 2 + 255) / 256;
    const int DWPREP    = (4 * 72 * 64 + 255) / 256;

    // input transforms (independent)
    concat_nhwc128_kernel<<<tgrid, tb>>>(neibor, target, nhwc128);
    nhwc64_kernel<<<tgrid, tb>>>(neibor, nhwcN);

    // 1. fea1 = conv_cr(concat)  -> bufA (NHWC64)
    wprep_kernel<<<WPREP_CR, tb>>>(cr_w, wph, wpl, 128, 64);
    conv_mma_kernel<64, 128, true><<<ggrid, tb, SM_CR>>>(nhwc128, wph, wpl, cr_b, bufA);

    // 2. o1 = off1(fea1) -> offb (NCHW); fea2 = deform(fea1, o1) -> bufB
    wprep_kernel<<<WPREP_OFF, tb>>>(off1_w, wph, wpl, 64, 144);
    conv_mma_kernel<144, 64, false><<<ggrid, tb, SM_OFF>>>(bufA, wph, wpl, off1_b, offb);
    dwprep_kernel<<<DWPREP, tb>>>(d1_w, dwph, dwpl);
    deform_kernel<false><<<dg, tb, SM_DEF>>>(bufA, offb, dwph, dwpl, d1_b, bufB);

    // 3. o2 = off2(fea2); fea3 = deform(fea2, o2) -> bufA
    wprep_kernel<<<WPREP_OFF, tb>>>(off2_w, wph, wpl, 64, 144);
    conv_mma_kernel<144, 64, false><<<ggrid, tb, SM_OFF>>>(bufB, wph, wpl, off2_b, offb);
    dwprep_kernel<<<DWPREP, tb>>>(d2_w, dwph, dwpl);
    deform_kernel<false><<<dg, tb, SM_DEF>>>(bufB, offb, dwph, dwpl, d2_b, bufA);

    // 4. o3 = off3(fea3); fea4 = deform(neibor, o3) -> bufB
    wprep_kernel<<<WPREP_OFF, tb>>>(off3_w, wph, wpl, 64, 144);
    conv_mma_kernel<144, 64, false><<<ggrid, tb, SM_OFF>>>(bufA, wph, wpl, off3_b, offb);
    dwprep_kernel<<<DWPREP, tb>>>(d3_w, dwph, dwpl);
    deform_kernel<false><<<dg, tb, SM_DEF>>>(nhwcN, offb, dwph, dwpl, d3_b, bufB);

    // 5. o4 = off4(fea4); aligned = deform(fea4, o4) -> d_out (NCHW)
    wprep_kernel<<<WPREP_OFF, tb>>>(off4_w, wph, wpl, 64, 144);
    conv_mma_kernel<144, 64, false><<<ggrid, tb, SM_OFF>>>(bufB, wph, wpl, off4_b, offb);
    dwprep_kernel<<<DWPREP, tb>>>(d4_w, dwph, dwpl);
    deform_kernel<true><<<dg, tb, SM_DEF>>>(bufB, offb, dwph, dwpl, d4_b, out);
}

// round 10
// speedup vs baseline: 1.7394x; 1.1395x over previous
#include <cuda_runtime.h>
#include <cuda_bf16.h>
#include <math.h>
#include <stdint.h>

#define HH 128
#define WW 128
#define NB 4
#define HW (HH * WW)

// ---------------- scratch (static device arrays; no allocation) ------------
__device__ float g_bufA[NB * 64 * HW];      // NHWC64 feature buffer
__device__ float g_bufB[NB * 64 * HW];      // NHWC64 feature buffer
__device__ float g_offb[NB * 144 * HW];     // offsets, NCHW
__device__ float g_nhwc128[NB * 128 * HW];  // concat(neibor,target) NHWC128
__device__ float g_nhwcN[NB * 64 * HW];     // neibor NHWC64
__device__ uint32_t g_wph[73728];           // conv weights hi, packed bf16x2 words
__device__ uint32_t g_wpl[73728];           // conv weights lo, packed bf16x2 words
__device__ uint32_t g_dwph[18432];          // deform weights hi, packed
__device__ uint32_t g_dwpl[18432];          // deform weights lo, packed

// ---------------- helpers ---------------------------------------------------
// split a float pair into packed bf16x2 hi word + lo word (even elem low half)
__device__ __forceinline__ void split2(float v0, float v1,
                                       uint32_t& hw, uint32_t& lw) {
    __nv_bfloat16 h0 = __float2bfloat16_rn(v0);
    __nv_bfloat16 h1 = __float2bfloat16_rn(v1);
    float l0 = v0 - __bfloat162float(h0);
    float l1 = v1 - __bfloat162float(h1);
    __nv_bfloat162 hp = __halves2bfloat162(h0, h1);
    __nv_bfloat162 lp = __floats2bfloat162_rn(l0, l1);
    hw = *(uint32_t*)&hp;
    lw = *(uint32_t*)&lp;
}
__device__ __forceinline__ void mma16(float* c, const uint32_t* a,
                                      uint32_t b0, uint32_t b1) {
    asm volatile(
        "mma.sync.aligned.m16n8k16.row.col.f32.bf16.bf16.f32 "
        "{%0,%1,%2,%3}, {%4,%5,%6,%7}, {%8,%9}, {%0,%1,%2,%3};"
        : "+f"(c[0]), "+f"(c[1]), "+f"(c[2]), "+f"(c[3])
        : "r"(a[0]), "r"(a[1]), "r"(a[2]), "r"(a[3]), "r"(b0), "r"(b1));
}
__device__ __forceinline__ void ldm_x4(uint32_t* r, uint32_t saddr) {
    asm volatile(
        "ldmatrix.sync.aligned.m8n8.x4.shared.b16 {%0,%1,%2,%3}, [%4];"
        : "=r"(r[0]), "=r"(r[1]), "=r"(r[2]), "=r"(r[3]) : "r"(saddr));
}
__device__ __forceinline__ void ldm_x2(uint32_t* r, uint32_t saddr) {
    asm volatile(
        "ldmatrix.sync.aligned.m8n8.x2.shared.b16 {%0,%1}, [%2];"
        : "=r"(r[0]), "=r"(r[1]) : "r"(saddr));
}

// ---------------------------------------------------------------------------
// Transforms
// ---------------------------------------------------------------------------
__global__ __launch_bounds__(256) void concat_nhwc128_kernel(
    const float* __restrict__ n, const float* __restrict__ t, float* __restrict__ out)
{
    int idx = blockIdx.x * 256 + threadIdx.x;   // NB*HW
    int b  = idx >> 14;
    int yx = idx & (HW - 1);
    const float* s0 = n + (size_t)b * 64 * HW + yx;
    const float* s1 = t + (size_t)b * 64 * HW + yx;
    float* o = out + (size_t)idx * 128;
#pragma unroll 8
    for (int c = 0; c < 64; c++) o[c] = s0[(size_t)c * HW];
#pragma unroll 8
    for (int c = 0; c < 64; c++) o[64 + c] = s1[(size_t)c * HW];
}

__global__ __launch_bounds__(256) void nhwc64_kernel(
    const float* __restrict__ in, float* __restrict__ out)
{
    int idx = blockIdx.x * 256 + threadIdx.x;
    int b  = idx >> 14;
    int yx = idx & (HW - 1);
    const float* s = in + (size_t)b * 64 * HW + yx;
    float* o = out + (size_t)idx * 64;
#pragma unroll 8
    for (int c = 0; c < 64; c++) o[c] = s[(size_t)c * HW];
}

// conv weight prep: w[oc][ic][3][3] -> packed bf16x2 hi/lo words laid out as
// [chunk ch][kg][oc][8 words], ch = (kpos, ich), kg = 16-ch half of the chunk.
__global__ void wprep_kernel(const float* __restrict__ w, uint32_t* __restrict__ wph,
                             uint32_t* __restrict__ wpl, int C_IN, int C_OUT)
{
    int i = blockIdx.x * 256 + threadIdx.x;
    int tot = C_OUT * C_IN * 9 / 2;
    if (i >= tot) return;
    int wd = i & 7;
    int t  = i >> 3;
    int oc = t % C_OUT;
    int t2 = t / C_OUT;
    int kg = t2 & 1;
    int ch = t2 >> 1;
    int ICH = C_IN / 32;
    int kpos = ch / ICH;
    int ich  = ch % ICH;
    int ic = ich * 32 + kg * 16 + wd * 2;
    float v0 = w[((size_t)oc * C_IN + ic) * 9 + kpos];
    float v1 = w[((size_t)oc * C_IN + ic + 1) * 9 + kpos];
    uint32_t hw, lw;
    split2(v0, v1, hw, lw);
    wph[i] = hw;
    wpl[i] = lw;
}

// deform weight prep: w[oc][ic][9] -> packed words [(dgc*72 + wdx)*64 + oc]
__global__ void dwprep_kernel(const float* __restrict__ w, uint32_t* __restrict__ dwph,
                              uint32_t* __restrict__ dwpl)
{
    int i = blockIdx.x * 256 + threadIdx.x;
    if (i >= 4 * 72 * 64) return;
    int oc  = i & 63;
    int t   = i >> 6;
    int wdx = t % 72;
    int dgc = t / 72;
    int dgl = wdx / 36;
    int rem = wdx % 36;
    int k   = rem >> 2;
    int wp  = rem & 3;
    int ic0 = (dgc * 2 + dgl) * 8 + wp * 2;
    float v0 = w[((size_t)oc * 64 + ic0) * 9 + k];
    float v1 = w[((size_t)oc * 64 + ic0 + 1) * 9 + k];
    uint32_t hw, lw;
    split2(v0, v1, hw, lw);
    dwph[i] = hw;
    dwpl[i] = lw;
}

// ---------------------------------------------------------------------------
// mma.sync bf16 implicit-GEMM 3x3 conv, v2:
//  - outer loop over dy: stage a 130-px halo row ONCE per (dy, ich); the 3 dx
//    taps reuse it via row-shifted ldmatrix fragment loads (3x less staging).
//  - ldmatrix.x4 fragment loads (8x fewer smem instructions than scalar LDS).
//  A layout: [p][ch-words], p = x+1 in 0..129, row stride 20 words
//  B layout: [kp][oc][16 words], row stride 20, 3 k-positions resident.
// ---------------------------------------------------------------------------
template <int N_OC, int C_IN, bool NHWC_OUT>
__global__ __launch_bounds__(256)
void conv_mma_kernel(const float* __restrict__ in, const uint32_t* __restrict__ wph,
                     const uint32_t* __restrict__ wpl, const float* __restrict__ bias,
                     float* __restrict__ out)
{
    extern __shared__ __align__(16) uint32_t SM[];
    constexpr int ICH  = C_IN / 32;            // ic-chunks per k position
    constexpr int RST  = 20;                   // word row stride
    constexpr int A_HI = 0;
    constexpr int A_LO = A_HI + 130 * RST;
    constexpr int B_HI = A_LO + 130 * RST;
    constexpr int B_LO = B_HI + 3 * N_OC * RST;
    constexpr int NA   = N_OC / 16;            // n-atoms per warp (9 or 4)

    const int tid  = threadIdx.x;
    const int lane = tid & 31;
    const int wid  = tid >> 5;
    const int m0   = (wid & 3) * 32;           // 4 M-tiles of 32 px
    const int n0   = (wid >> 2) * (N_OC / 2);  // 2 N-halves

    const int r = blockIdx.x;
    const int b = r >> 7;
    const int y = r & 127;

    const int quad = lane >> 3;                // ldmatrix lane decode
    const int lr   = lane & 7;

    float acc[2][NA][4];
#pragma unroll
    for (int m = 0; m < 2; m++)
#pragma unroll
        for (int na = 0; na < NA; na++)
#pragma unroll
            for (int q = 0; q < 4; q++) acc[m][na][q] = 0.0f;

    for (int dy = 0; dy < 3; dy++) {
        const int yy = y + dy - 1;
        const bool rv = (yy >= 0) && (yy < HH);

        for (int ich = 0; ich < ICH; ich++) {
            // ---- stage A: 130 px (x = -1..128) x 32 ch, hi/lo split ----
            for (int t = tid; t < 260; t += 256) {
                int p  = t >> 1;
                int kg = t & 1;
                int x  = p - 1;
                bool val = rv && (x >= 0) && (x < WW);
                const float4* src = (const float4*)(in +
                    (((size_t)b * HW + (size_t)yy * WW + x) * C_IN + ich * 32 + kg * 16));
                int abase = p * RST + kg * 8;
#pragma unroll
                for (int j = 0; j < 4; j++) {
                    float4 v = val ? src[j] : make_float4(0.f, 0.f, 0.f, 0.f);
                    uint32_t h0, l0, h1, l1;
                    split2(v.x, v.y, h0, l0);
                    split2(v.z, v.w, h1, l1);
                    *(uint2*)&SM[A_HI + abase + 2 * j] = make_uint2(h0, h1);
                    *(uint2*)&SM[A_LO + abase + 2 * j] = make_uint2(l0, l1);
                }
            }
            // ---- stage B: 3 k-positions of this ich (pre-packed copy) ----
            for (int t = tid; t < 3 * N_OC * 16; t += 256) {
                int kp  = t / (N_OC * 16);
                int rem = t - kp * (N_OC * 16);
                int n   = rem >> 4;
                int w16 = rem & 15;
                int kg  = w16 >> 3;
                int wd  = w16 & 7;
                int gsrc = ((((dy * 3 + kp) * ICH + ich) * 2 + kg) * N_OC + n) * 8 + wd;
                int o = (kp * N_OC + n) * RST + w16;
                SM[B_HI + o] = wph[gsrc];
                SM[B_LO + o] = wpl[gsrc];
            }
            __syncthreads();

            // ---- compute: 3 dx taps x 2 k16 groups ----
#pragma unroll
            for (int dx = 0; dx < 3; dx++) {
#pragma unroll
                for (int kg = 0; kg < 2; kg++) {
                    // A fragments (2 m-atoms) via ldmatrix.x4
                    uint32_t ah[2][4], al[2][4];
#pragma unroll
                    for (int m = 0; m < 2; m++) {
                        int row = m0 + m * 16 + dx + (quad & 1) * 8 + lr;
                        int wi  = row * RST + kg * 8 + (quad >> 1) * 4;
                        ldm_x4(ah[m], (uint32_t)__cvta_generic_to_shared(&SM[A_HI + wi]));
                        ldm_x4(al[m], (uint32_t)__cvta_generic_to_shared(&SM[A_LO + wi]));
                    }
                    // B fragments in pairs of n-atoms, consumed immediately
#pragma unroll
                    for (int p2 = 0; p2 < NA - 1; p2 += 2) {
                        int rowb = dx * N_OC + n0 + p2 * 8 + (quad >> 1) * 8 + lr;
                        int wi   = rowb * RST + kg * 8 + (quad & 1) * 4;
                        uint32_t bh[4], bl[4];
                        ldm_x4(bh, (uint32_t)__cvta_generic_to_shared(&SM[B_HI + wi]));
                        ldm_x4(bl, (uint32_t)__cvta_generic_to_shared(&SM[B_LO + wi]));
#pragma unroll
                        for (int m = 0; m < 2; m++) {
                            mma16(acc[m][p2], ah[m], bh[0], bh[1]);
                            mma16(acc[m][p2], ah[m], bl[0], bl[1]);
                            mma16(acc[m][p2], al[m], bh[0], bh[1]);
                            mma16(acc[m][p2 + 1], ah[m], bh[2], bh[3]);
                            mma16(acc[m][p2 + 1], ah[m], bl[2], bl[3]);
                            mma16(acc[m][p2 + 1], al[m], bh[2], bh[3]);
                        }
                    }
                    if (NA & 1) {              // tail n-atom (NA = 9)
                        int p2 = NA - 1;
                        int rowb = dx * N_OC + n0 + p2 * 8 + lr;
                        int wi   = rowb * RST + kg * 8 + (quad & 1) * 4;
                        // x2 uses lanes 0..15; quad>=2 lanes provide dummy
                        // (valid) addresses within the same rows.
                        uint32_t bh[2], bl[2];
                        ldm_x2(bh, (uint32_t)__cvta_generic_to_shared(&SM[B_HI + wi]));
                        ldm_x2(bl, (uint32_t)__cvta_generic_to_shared(&SM[B_LO + wi]));
#pragma unroll
                        for (int m = 0; m < 2; m++) {
                            mma16(acc[m][p2], ah[m], bh[0], bh[1]);
                            mma16(acc[m][p2], ah[m], bl[0], bl[1]);
                            mma16(acc[m][p2], al[m], bh[0], bh[1]);
                        }
                    }
                }
            }
            __syncthreads();
        }
    }

    // ---- epilogue ----
#pragma unroll
    for (int m = 0; m < 2; m++) {
        int x0 = m0 + m * 16 + (lane >> 2);
#pragma unroll
        for (int na = 0; na < NA; na++) {
            int n = n0 + na * 8 + 2 * (lane & 3);
            float b0 = __ldg(&bias[n]);
            float b1 = __ldg(&bias[n + 1]);
            if (NHWC_OUT) {
                float* op0 = out + ((size_t)b * HW + (size_t)y * WW + x0) * N_OC + n;
                float* op1 = op0 + 8 * N_OC;
                *(float2*)op0 = make_float2(acc[m][na][0] + b0, acc[m][na][1] + b1);
                *(float2*)op1 = make_float2(acc[m][na][2] + b0, acc[m][na][3] + b1);
            } else {
                size_t base = (size_t)b * N_OC * HW + (size_t)y * WW + x0;
                out[base + (size_t)n * HW]           = acc[m][na][0] + b0;
                out[base + (size_t)(n + 1) * HW]     = acc[m][na][1] + b1;
                out[base + (size_t)n * HW + 8]       = acc[m][na][2] + b0;
                out[base + (size_t)(n + 1) * HW + 8] = acc[m][na][3] + b1;
            }
        }
    }
}

// ---------------------------------------------------------------------------
// Deformable conv: fp32 bilinear gather (NHWC64 source) -> bf16 hi/lo cols in
// smem -> m16n8k16 MMA GEMM (3-term split). Block: 64 px (8x8), 64 oc, one b.
// (unchanged from round 9 — verified win)
// ---------------------------------------------------------------------------
template <bool NCHW_OUT>
__global__ __launch_bounds__(256)
void deform_kernel(const float* __restrict__ src, const float* __restrict__ off,
                   const uint32_t* __restrict__ dwph, const uint32_t* __restrict__ dwpl,
                   const float* __restrict__ bias, float* __restrict__ out)
{
    extern __shared__ __align__(16) uint32_t SM[];
    constexpr int RST   = 72;                 // padded row length (64 + 8)
    constexpr int PLANE = 72 * RST;           // 72 w-rows
    constexpr int A_HI = 0;
    constexpr int A_LO = A_HI + PLANE;
    constexpr int B_HI = A_LO + PLANE;
    constexpr int B_LO = B_HI + PLANE;

    const int tid  = threadIdx.x;
    const int lane = tid & 31;
    const int wid  = tid >> 5;
    const int m0   = (wid & 3) * 16;          // 4 m-tiles of 16 px
    const int n0   = (wid >> 2) * 32;         // 2 n-halves of 32 oc

    const int b   = blockIdx.z;
    const int bx0 = blockIdx.x * 8;
    const int by0 = blockIdx.y * 8;

    float acc[4][4];
#pragma unroll
    for (int na = 0; na < 4; na++)
#pragma unroll
        for (int q = 0; q < 4; q++) acc[na][q] = 0.0f;

    for (int dgc = 0; dgc < 4; dgc++) {
        // ---- stage B: coalesced copy of pre-packed weights ----
        for (int t = tid; t < 72 * 64; t += 256) {
            int w  = t >> 6;
            int oc = t & 63;
            int g  = ((dgc * 72 + w) << 6) + oc;
            int o  = w * RST + oc;
            SM[B_HI + o] = dwph[g];
            SM[B_LO + o] = dwpl[g];
        }
        // ---- stage A: bilinear gather + bf16 split ----
        for (int t = tid; t < 1152; t += 256) {
            int px   = t & 63;
            int rest = t >> 6;          // 0..17
            int k    = rest % 9;
            int dgl  = rest / 9;        // 0..1
            int dg   = dgc * 2 + dgl;

            int yy = by0 + (px >> 3);
            int xx = bx0 + (px & 7);

            int offch = (dg * 9 + k) * 2;
            size_t obase = (((size_t)b * 144 + offch) * HH + yy) * WW + xx;
            float dy = off[obase];
            float dx = off[obase + (size_t)HW];

            float py  = dy + (float)yy + (float)(k / 3 - 1);
            float pxc = dx + (float)xx + (float)(k % 3 - 1);
            float y0f = floorf(py);
            float x0f = floorf(pxc);
            float wy = py - y0f;
            float wx = pxc - x0f;
            int y0 = (int)y0f;
            int x0 = (int)x0f;

            float w00 = (1.0f - wy) * (1.0f - wx);
            float w01 = (1.0f - wy) * wx;
            float w10 = wy * (1.0f - wx);
            float w11 = wy * wx;

            bool vy0 = ((unsigned)y0 < (unsigned)HH);
            bool vy1 = ((unsigned)(y0 + 1) < (unsigned)HH);
            bool vx0 = ((unsigned)x0 < (unsigned)WW);
            bool vx1 = ((unsigned)(x0 + 1) < (unsigned)WW);
            w00 *= (float)(vy0 && vx0);
            w01 *= (float)(vy0 && vx1);
            w10 *= (float)(vy1 && vx0);
            w11 *= (float)(vy1 && vx1);

            int y0c = min(max(y0, 0), HH - 1);
            int y1c = min(max(y0 + 1, 0), HH - 1);
            int x0c = min(max(x0, 0), WW - 1);
            int x1c = min(max(x0 + 1, 0), WW - 1);

            const float* base = src + (size_t)b * HW * 64 + dg * 8;
            const float4* p00 = (const float4*)(base + (size_t)(y0c * WW + x0c) * 64);
            const float4* p01 = (const float4*)(base + (size_t)(y0c * WW + x1c) * 64);
            const float4* p10 = (const float4*)(base + (size_t)(y1c * WW + x0c) * 64);
            const float4* p11 = (const float4*)(base + (size_t)(y1c * WW + x1c) * 64);

            float4 a00 = p00[0], b00 = p00[1];
            float4 a01 = p01[0], b01 = p01[1];
            float4 a10 = p10[0], b10 = p10[1];
            float4 a11 = p11[0], b11 = p11[1];

            float v0 = w00 * a00.x + w01 * a01.x + w10 * a10.x + w11 * a11.x;
            float v1 = w00 * a00.y + w01 * a01.y + w10 * a10.y + w11 * a11.y;
            float v2 = w00 * a00.z + w01 * a01.z + w10 * a10.z + w11 * a11.z;
            float v3 = w00 * a00.w + w01 * a01.w + w10 * a10.w + w11 * a11.w;
            float v4 = w00 * b00.x + w01 * b01.x + w10 * b10.x + w11 * b11.x;
            float v5 = w00 * b00.y + w01 * b01.y + w10 * b10.y + w11 * b11.y;
            float v6 = w00 * b00.z + w01 * b01.z + w10 * b10.z + w11 * b11.z;
            float v7 = w00 * b00.w + w01 * b01.w + w10 * b10.w + w11 * b11.w;

            int w0 = dgl * 36 + k * 4;       // word row base
            uint32_t h, l;
            split2(v0, v1, h, l);
            SM[A_HI + (w0 + 0) * RST + px] = h;
            SM[A_LO + (w0 + 0) * RST + px] = l;
            split2(v2, v3, h, l);
            SM[A_HI + (w0 + 1) * RST + px] = h;
            SM[A_LO + (w0 + 1) * RST + px] = l;
            split2(v4, v5, h, l);
            SM[A_HI + (w0 + 2) * RST + px] = h;
            SM[A_LO + (w0 + 2) * RST + px] = l;
            split2(v6, v7, h, l);
            SM[A_HI + (w0 + 3) * RST + px] = h;
            SM[A_LO + (w0 + 3) * RST + px] = l;
        }
        __syncthreads();

        // ---- compute: 9 k16 groups of this 144-K chunk ----
        const int rr = lane >> 2;
        const int c  = lane & 3;
#pragma unroll
        for (int g = 0; g < 9; g++) {
            int wA0 = (g * 8 + c) * RST;
            int wA1 = (g * 8 + c + 4) * RST;
            int row0 = m0 + rr;
            int row1 = m0 + rr + 8;
            uint32_t ah[4], al[4];
            ah[0] = SM[A_HI + wA0 + row0];
            ah[1] = SM[A_HI + wA0 + row1];
            ah[2] = SM[A_HI + wA1 + row0];
            ah[3] = SM[A_HI + wA1 + row1];
            al[0] = SM[A_LO + wA0 + row0];
            al[1] = SM[A_LO + wA0 + row1];
            al[2] = SM[A_LO + wA1 + row0];
            al[3] = SM[A_LO + wA1 + row1];
#pragma unroll
            for (int na = 0; na < 4; na++) {
                int nn = n0 + na * 8 + rr;
                uint32_t bh0 = SM[B_HI + wA0 + nn];
                uint32_t bh1 = SM[B_HI + wA1 + nn];
                uint32_t bl0 = SM[B_LO + wA0 + nn];
                uint32_t bl1 = SM[B_LO + wA1 + nn];
                mma16(acc[na], ah, bh0, bh1);
                mma16(acc[na], ah, bl0, bl1);
                mma16(acc[na], al, bh0, bh1);
            }
        }
        __syncthreads();
    }

    // ---- epilogue ----
    const int rr = lane >> 2;
    const int c  = lane & 3;
#pragma unroll
    for (int na = 0; na < 4; na++) {
        int n = n0 + na * 8 + 2 * c;
        float b0 = __ldg(&bias[n]);
        float b1 = __ldg(&bias[n + 1]);
#pragma unroll
        for (int h = 0; h < 2; h++) {
            int px = m0 + rr + h * 8;
            int y = by0 + (px >> 3);
            int x = bx0 + (px & 7);
            float r0 = acc[na][h * 2 + 0] + b0;
            float r1 = acc[na][h * 2 + 1] + b1;
            if (NCHW_OUT) {
                size_t base = ((size_t)b * 64) * HW + (size_t)y * WW + x;
                out[base + (size_t)n * HW]       = r0;
                out[base + (size_t)(n + 1) * HW] = r1;
            } else {
                *(float2*)&out[((size_t)b * HW + (size_t)y * WW + x) * 64 + n] =
                    make_float2(r0, r1);
            }
        }
    }
}

// ---------------------------------------------------------------------------
extern "C" void kernel_launch(void* const* d_in, const int* in_sizes, int n_in,
                              void* d_out, int out_size)
{
    const float* neibor = (const float*)d_in[0];
    const float* target = (const float*)d_in[1];
    const float* cr_w   = (const float*)d_in[2];
    const float* cr_b   = (const float*)d_in[3];
    const float* off1_w = (const float*)d_in[4];
    const float* off1_b = (const float*)d_in[5];
    const float* d1_w   = (const float*)d_in[6];
    const float* d1_b   = (const float*)d_in[7];
    const float* off2_w = (const float*)d_in[8];
    const float* off2_b = (const float*)d_in[9];
    const float* d2_w   = (const float*)d_in[10];
    const float* d2_b   = (const float*)d_in[11];
    const float* off3_w = (const float*)d_in[12];
    const float* off3_b = (const float*)d_in[13];
    const float* d3_w   = (const float*)d_in[14];
    const float* d3_b   = (const float*)d_in[15];
    const float* off4_w = (const float*)d_in[16];
    const float* off4_b = (const float*)d_in[17];
    const float* d4_w   = (const float*)d_in[18];
    const float* d4_b   = (const float*)d_in[19];
    float* out = (float*)d_out;

    float *bufA, *bufB, *offb, *nhwc128, *nhwcN;
    uint32_t *wph, *wpl, *dwph, *dwpl;
    cudaGetSymbolAddress((void**)&bufA,    g_bufA);
    cudaGetSymbolAddress((void**)&bufB,    g_bufB);
    cudaGetSymbolAddress((void**)&offb,    g_offb);
    cudaGetSymbolAddress((void**)&nhwc128, g_nhwc128);
    cudaGetSymbolAddress((void**)&nhwcN,   g_nhwcN);
    cudaGetSymbolAddress((void**)&wph,     g_wph);
    cudaGetSymbolAddress((void**)&wpl,     g_wpl);
    cudaGetSymbolAddress((void**)&dwph,    g_dwph);
    cudaGetSymbolAddress((void**)&dwpl,    g_dwpl);

    // dynamic smem (bytes): A 2*130*20 words + B 2*3*N_OC*20 words
    const int SM_CR  = (2 * 130 * 20 + 2 * 3 * 64 * 20) * 4;    // 51520
    const int SM_OFF = (2 * 130 * 20 + 2 * 3 * 144 * 20) * 4;   // 89920
    const int SM_DEF = 4 * 72 * 72 * 4;                         // 82944
    cudaFuncSetAttribute(conv_mma_kernel<64, 128, true>,
                         cudaFuncAttributeMaxDynamicSharedMemorySize, SM_CR);
    cudaFuncSetAttribute(conv_mma_kernel<144, 64, false>,
                         cudaFuncAttributeMaxDynamicSharedMemorySize, SM_OFF);
    cudaFuncSetAttribute(deform_kernel<false>,
                         cudaFuncAttributeMaxDynamicSharedMemorySize, SM_DEF);
    cudaFuncSetAttribute(deform_kernel<true>,
                         cudaFuncAttributeMaxDynamicSharedMemorySize, SM_DEF);

    dim3 tb(256);
    dim3 dg(WW / 8, HH / 8, NB);                // deform grid
    const int ggrid = NB * HH;                  // 512 conv-GEMM blocks
    const int tgrid = NB * HW / 256;            // transform blocks
    const int WPREP_CR  = (64 * 1152 / 2 + 255) / 256;
    const int WPREP_OFF = (144 * 576 / 2 + 255) / 256;
    const int DWPREP    = (4 * 72 * 64 + 255) / 256;

    // input transforms (independent)
    concat_nhwc128_kernel<<<tgrid, tb>>>(neibor, target, nhwc128);
    nhwc64_kernel<<<tgrid, tb>>>(neibor, nhwcN);

    // 1. fea1 = conv_cr(concat)  -> bufA (NHWC64)
    wprep_kernel<<<WPREP_CR, tb>>>(cr_w, wph, wpl, 128, 64);
    conv_mma_kernel<64, 128, true><<<ggrid, tb, SM_CR>>>(nhwc128, wph, wpl, cr_b, bufA);

    // 2. o1 = off1(fea1) -> offb (NCHW); fea2 = deform(fea1, o1) -> bufB
    wprep_kernel<<<WPREP_OFF, tb>>>(off1_w, wph, wpl, 64, 144);
    conv_mma_kernel<144, 64, false><<<ggrid, tb, SM_OFF>>>(bufA, wph, wpl, off1_b, offb);
    dwprep_kernel<<<DWPREP, tb>>>(d1_w, dwph, dwpl);
    deform_kernel<false><<<dg, tb, SM_DEF>>>(bufA, offb, dwph, dwpl, d1_b, bufB);

    // 3. o2 = off2(fea2); fea3 = deform(fea2, o2) -> bufA
    wprep_kernel<<<WPREP_OFF, tb>>>(off2_w, wph, wpl, 64, 144);
    conv_mma_kernel<144, 64, false><<<ggrid, tb, SM_OFF>>>(bufB, wph, wpl, off2_b, offb);
    dwprep_kernel<<<DWPREP, tb>>>(d2_w, dwph, dwpl);
    deform_kernel<false><<<dg, tb, SM_DEF>>>(bufB, offb, dwph, dwpl, d2_b, bufA);

    // 4. o3 = off3(fea3); fea4 = deform(neibor, o3) -> bufB
    wprep_kernel<<<WPREP_OFF, tb>>>(off3_w, wph, wpl, 64, 144);
    conv_mma_kernel<144, 64, false><<<ggrid, tb, SM_OFF>>>(bufA, wph, wpl, off3_b, offb);
    dwprep_kernel<<<DWPREP, tb>>>(d3_w, dwph, dwpl);
    deform_kernel<false><<<dg, tb, SM_DEF>>>(nhwcN, offb, dwph, dwpl, d3_b, bufB);

    // 5. o4 = off4(fea4); aligned = deform(fea4, o4) -> d_out (NCHW)
    wprep_kernel<<<WPREP_OFF, tb>>>(off4_w, wph, wpl, 64, 144);
    conv_mma_kernel<144, 64, false><<<ggrid, tb, SM_OFF>>>(bufB, wph, wpl, off4_b, offb);
    dwprep_kernel<<<DWPREP, tb>>>(d4_w, dwph, dwpl);
    deform_kernel<true><<<dg, tb, SM_DEF>>>(bufB, offb, dwph, dwpl, d4_b, out);
}